// round 10
// baseline (speedup 1.0000x reference)
#include <cuda_runtime.h>
#include <cuda_bf16.h>
#include <math.h>
#include <stdint.h>

#define BB 4
#define NN 4096
#define NFF 8192
#define KK 512
#define CC 128
#define LL 4
#define INDIM 3
#define FCD 128
#define FWD_S 2

typedef __nv_bfloat16 bf16;
typedef __nv_bfloat162 bf162;

// -------- scratch --------
__device__ bf16  g_Bc [BB*KK*NN];      // basis [b][k][n]
__device__ bf16  g_Bs [BB*KK*NN];
__device__ bf16  g_BcT[BB*NN*KK];      // basis [b][n][k]
__device__ bf16  g_BsT[BB*NN*KK];
__device__ float g_wqn[BB*NN];
__device__ float g_h[2][BB*CC*NN];
__device__ bf16  g_hwb[BB*CC*NN];      // h0*wqn bf16
__device__ float g_pc[FWD_S][BB*CC*KK];  // forward partials (consumed by mix)
__device__ float g_ps[FWD_S][BB*CC*KK];
__device__ bf16  g_fAb[LL][BB*CC*KK];
__device__ bf16  g_fBb[LL][BB*CC*KK];
__device__ bf16  g_x1b[LL][BB*CC*NN];  // spectral inverse, bf16
__device__ float g_x0h[BB*CC];
__device__ float g_f0h[LL][BB*CC];

__device__ __forceinline__ float gelu_exact(float v) {
    return 0.5f * v * (1.0f + erff(v * 0.7071067811865476f));
}
__device__ __forceinline__ float tf32r(float x) {
    float r;
    asm("cvt.rna.tf32.f32 %0, %1;" : "=f"(r) : "f"(x));
    return r;
}
__device__ __forceinline__ void split_tf32(float v, float& hi, float& lo) {
    hi = tf32r(v);
    lo = tf32r(v - hi);
}
__device__ __forceinline__ void mma_tf32(float (&d)[4], const uint32_t (&a)[4],
                                         const uint32_t (&b)[2]) {
    asm volatile(
        "mma.sync.aligned.m16n8k8.row.col.f32.tf32.tf32.f32 "
        "{%0,%1,%2,%3}, {%4,%5,%6,%7}, {%8,%9}, {%0,%1,%2,%3};"
        : "+f"(d[0]), "+f"(d[1]), "+f"(d[2]), "+f"(d[3])
        : "r"(a[0]), "r"(a[1]), "r"(a[2]), "r"(a[3]), "r"(b[0]), "r"(b[1]));
}
__device__ __forceinline__ void mma_bf16(float (&d)[4], const uint32_t (&a)[4],
                                         const uint32_t (&b)[2]) {
    asm volatile(
        "mma.sync.aligned.m16n8k16.row.col.f32.bf16.bf16.f32 "
        "{%0,%1,%2,%3}, {%4,%5,%6,%7}, {%8,%9}, {%0,%1,%2,%3};"
        : "+f"(d[0]), "+f"(d[1]), "+f"(d[2]), "+f"(d[3])
        : "r"(a[0]), "r"(a[1]), "r"(a[2]), "r"(a[3]), "r"(b[0]), "r"(b[1]));
}

// -------- K1: basis via integer-mode angle addition + fused wqn --------
__global__ void k_basis(const float* __restrict__ xf, const int* __restrict__ ind,
                        const float* __restrict__ modes) {
    __shared__ float txC[33][32], txS[33][32], tyC[33][32], tyS[33][32];
    __shared__ bf16 tc[32][34], ts[32][34];
    int b  = blockIdx.y;
    int n0 = blockIdx.x * 32;
    int tid = threadIdx.x;
    int tx = tid & 31;
    int ty = tid >> 5;
    if (ty == 0) {
        int n = n0 + tx;
        int f = __ldg(&ind[n]);
        const float* xfp = xf + ((size_t)b*NFF + f)*4;
        float gx = __ldg(&xfp[0]);
        float gy = __ldg(&xfp[1]);
        g_wqn[b*NN + n] = __ldg(&xfp[2]) * (float)NN;
        float c1, s1;
        sincosf(gx, &s1, &c1);
        txC[16][tx] = 1.f; txS[16][tx] = 0.f;
        float cj = c1, sj = s1;
        #pragma unroll
        for (int j = 1; j <= 16; j++) {
            txC[16+j][tx] = cj;  txS[16+j][tx] = sj;
            txC[16-j][tx] = cj;  txS[16-j][tx] = -sj;
            float cn = cj*c1 - sj*s1;
            float sn = sj*c1 + cj*s1;
            cj = cn; sj = sn;
        }
        sincosf(gy, &s1, &c1);
        tyC[16][tx] = 1.f; tyS[16][tx] = 0.f;
        cj = c1; sj = s1;
        #pragma unroll
        for (int j = 1; j <= 16; j++) {
            tyC[16+j][tx] = cj;  tyS[16+j][tx] = sj;
            tyC[16-j][tx] = cj;  tyS[16-j][tx] = -sj;
            float cn = cj*c1 - sj*s1;
            float sn = sj*c1 + cj*s1;
            cj = cn; sj = sn;
        }
    }
    __syncthreads();
    for (int k0 = 0; k0 < KK; k0 += 32) {
        #pragma unroll
        for (int jj = 0; jj < 4; jj++) {
            int kr = ty*4 + jj;
            int k = k0 + kr;
            int jx = (int)__ldg(&modes[2*k])   + 16;
            int jy = (int)__ldg(&modes[2*k+1]) + 16;
            float ca = txC[jx][tx], sa = txS[jx][tx];
            float cb = tyC[jy][tx], sb = tyS[jy][tx];
            float c = ca*cb - sa*sb;
            float s = sa*cb + ca*sb;
            bf16 cb16 = __float2bfloat16(c);
            bf16 sb16 = __float2bfloat16(s);
            tc[kr][tx] = cb16;
            ts[kr][tx] = sb16;
            g_Bc[((size_t)b*KK + k)*NN + n0 + tx] = cb16;
            g_Bs[((size_t)b*KK + k)*NN + n0 + tx] = sb16;
        }
        __syncthreads();
        #pragma unroll
        for (int jj = 0; jj < 4; jj++) {
            int nr = ty*4 + jj;
            int n = n0 + nr;
            g_BcT[((size_t)b*NN + n)*KK + k0 + tx] = tc[tx][nr];
            g_BsT[((size_t)b*NN + n)*KK + k0 + tx] = ts[tx][nr];
        }
        __syncthreads();
    }
}

// -------- K2: fc0 --------
__global__ void k_fc0(const float* __restrict__ x, const float* __restrict__ w,
                      const float* __restrict__ bias) {
    int n = blockIdx.x * blockDim.x + threadIdx.x;
    int c = blockIdx.y;
    int b = blockIdx.z;
    const float* xp = x + ((size_t)b * NN + n) * INDIM;
    float acc = bias[c]
              + xp[0] * w[0*CC + c]
              + xp[1] * w[1*CC + c]
              + xp[2] * w[2*CC + c];
    size_t o = ((size_t)b*CC + c) * NN + n;
    g_h[0][o] = acc;
    g_hwb[o]  = __float2bfloat16(acc * g_wqn[b*NN + n]);
}

// -------- K2b: x0h --------
__global__ void k_x0h() {
    int bc = blockIdx.x;
    const bf162* p = reinterpret_cast<const bf162*>(g_hwb + (size_t)bc * NN);
    float acc = 0.f;
    for (int n = threadIdx.x; n < NN/2; n += 256) {
        float2 v = __bfloat1622float2(p[n]);
        acc += v.x + v.y;
    }
    __shared__ float red[256];
    red[threadIdx.x] = acc;
    __syncthreads();
    for (int s = 128; s > 0; s >>= 1) {
        if (threadIdx.x < s) red[threadIdx.x] += red[threadIdx.x + s];
        __syncthreads();
    }
    if (threadIdx.x == 0) g_x0h[bc] = red[0];
}

// -------- K3: forward dual GEMM, bf16 TC, split-N --------
__global__ void k_fwd_tc() {
    __shared__ bf16 As[32][72];
    __shared__ bf16 Bsm[2][64][72];
    int z   = blockIdx.z;
    int b   = z >> 1;
    int s   = z & 1;
    int m0  = blockIdx.y * 32;
    int ko0 = blockIdx.x * 64;
    int tid = threadIdx.x;
    int lane = tid & 31, wid = tid >> 5;
    int wm = wid >> 2, wn = wid & 3;
    int g = lane >> 2, tig = lane & 3;
    float acc[2][2][4] = {};
    const bf16* A  = g_hwb + ((size_t)b*CC + m0) * NN + s * (NN/FWD_S);
    const bf16* Bc = g_Bc  + ((size_t)b*KK + ko0) * NN + s * (NN/FWD_S);
    const bf16* Bs = g_Bs  + ((size_t)b*KK + ko0) * NN + s * (NN/FWD_S);
    int arow = tid >> 3, ac8 = (tid & 7) * 8;
    for (int r0 = 0; r0 < NN/FWD_S; r0 += 64) {
        *(uint4*)&As[arow][ac8] = *(const uint4*)&A[(size_t)arow*NN + r0 + ac8];
        #pragma unroll
        for (int t = 0; t < 2; t++) {
            int brow = (tid >> 3) + t*32;
            *(uint4*)&Bsm[0][brow][ac8] = *(const uint4*)&Bc[(size_t)brow*NN + r0 + ac8];
            *(uint4*)&Bsm[1][brow][ac8] = *(const uint4*)&Bs[(size_t)brow*NN + r0 + ac8];
        }
        __syncthreads();
        #pragma unroll
        for (int kk = 0; kk < 64; kk += 16) {
            uint32_t af[4];
            int m = wm * 16;
            af[0] = *(const uint32_t*)&As[m+g  ][kk + 2*tig    ];
            af[1] = *(const uint32_t*)&As[m+g+8][kk + 2*tig    ];
            af[2] = *(const uint32_t*)&As[m+g  ][kk + 2*tig + 8];
            af[3] = *(const uint32_t*)&As[m+g+8][kk + 2*tig + 8];
            #pragma unroll
            for (int p = 0; p < 2; p++) {
                #pragma unroll
                for (int ns = 0; ns < 2; ns++) {
                    int n = wn * 16 + ns * 8;
                    uint32_t bf[2];
                    bf[0] = *(const uint32_t*)&Bsm[p][n+g][kk + 2*tig    ];
                    bf[1] = *(const uint32_t*)&Bsm[p][n+g][kk + 2*tig + 8];
                    mma_bf16(acc[p][ns], af, bf);
                }
            }
        }
        __syncthreads();
    }
    #pragma unroll
    for (int ns = 0; ns < 2; ns++) {
        int m = m0 + wm*16 + g;
        int k = ko0 + wn*16 + ns*8 + tig*2;
        size_t o0 = ((size_t)b*CC + m)*KK + k;
        size_t o1 = ((size_t)b*CC + m + 8)*KK + k;
        g_pc[s][o0]   = acc[0][ns][0];
        g_pc[s][o0+1] = acc[0][ns][1];
        g_pc[s][o1]   = acc[0][ns][2];
        g_pc[s][o1+1] = acc[0][ns][3];
        g_ps[s][o0]   = acc[1][ns][0];
        g_ps[s][o0+1] = acc[1][ns][1];
        g_ps[s][o1]   = acc[1][ns][2];
        g_ps[s][o1+1] = acc[1][ns][3];
    }
}

// -------- K4: mode mix (reads fwd partials; k-split 2; 64 thr; unroll 8) --------
__global__ void k_mix_all(const float* __restrict__ wc, const float* __restrict__ ws) {
    int o = blockIdx.x;
    int l = blockIdx.y;
    int k = blockIdx.z * (KK/2) + threadIdx.x * 4;
    const float inv_nf = 1.0f / (float)NFF;
    float4 accc[BB], accs[BB];
    #pragma unroll
    for (int b = 0; b < BB; b++) {
        accc[b] = make_float4(0.f,0.f,0.f,0.f);
        accs[b] = make_float4(0.f,0.f,0.f,0.f);
    }
    const float* wcp = wc + (((size_t)l*CC)*CC + o)*KK + k;
    const float* wsp = ws + (((size_t)l*CC)*CC + o)*KK + k;
    #pragma unroll 8
    for (int i = 0; i < CC; i++) {
        float4 wcv = *(const float4*)(wcp + (size_t)i*CC*KK);
        float4 wsv = *(const float4*)(wsp + (size_t)i*CC*KK);
        #pragma unroll
        for (int b = 0; b < BB; b++) {
            size_t xo = ((size_t)b*CC + i)*KK + k;
            float4 c0 = *(const float4*)(g_pc[0] + xo);
            float4 c1 = *(const float4*)(g_pc[1] + xo);
            float4 s0 = *(const float4*)(g_ps[0] + xo);
            float4 s1 = *(const float4*)(g_ps[1] + xo);
            float4 xc, xs;
            xc.x = c0.x+c1.x; xc.y = c0.y+c1.y; xc.z = c0.z+c1.z; xc.w = c0.w+c1.w;
            xs.x = s0.x+s1.x; xs.y = s0.y+s1.y; xs.z = s0.z+s1.z; xs.w = s0.w+s1.w;
            accc[b].x += xc.x*wcv.x + xs.x*wsv.x;
            accc[b].y += xc.y*wcv.y + xs.y*wsv.y;
            accc[b].z += xc.z*wcv.z + xs.z*wsv.z;
            accc[b].w += xc.w*wcv.w + xs.w*wsv.w;
            accs[b].x += xc.x*wsv.x - xs.x*wcv.x;
            accs[b].y += xc.y*wsv.y - xs.y*wcv.y;
            accs[b].z += xc.z*wsv.z - xs.z*wcv.z;
            accs[b].w += xc.w*wsv.w - xs.w*wcv.w;
        }
    }
    #pragma unroll
    for (int b = 0; b < BB; b++) {
        size_t o4 = ((size_t)b*CC + o)*KK + k;
        bf162* fa = reinterpret_cast<bf162*>(&g_fAb[l][o4]);
        bf162* fb = reinterpret_cast<bf162*>(&g_fBb[l][o4]);
        fa[0] = __floats2bfloat162_rn( 2.0f*inv_nf*accc[b].x,  2.0f*inv_nf*accc[b].y);
        fa[1] = __floats2bfloat162_rn( 2.0f*inv_nf*accc[b].z,  2.0f*inv_nf*accc[b].w);
        fb[0] = __floats2bfloat162_rn(-2.0f*inv_nf*accs[b].x, -2.0f*inv_nf*accs[b].y);
        fb[1] = __floats2bfloat162_rn(-2.0f*inv_nf*accs[b].z, -2.0f*inv_nf*accs[b].w);
    }
}

// -------- K4b: f0h --------
__global__ void k_f0h_all(const float* __restrict__ w0, const float* __restrict__ convb) {
    int l = blockIdx.x;
    int t = threadIdx.x;
    int b = t >> 7, o = t & 127;
    float acc = 0.f;
    #pragma unroll 4
    for (int i = 0; i < CC; i++)
        acc += g_x0h[b*CC + i] * __ldg(&w0[((size_t)l*CC + i)*CC + o]);
    g_f0h[l][t] = acc * (1.0f / (float)NFF) + convb[l*CC + o];
}

// -------- K5a: inverse spectral GEMM --------
__global__ void k_inv_spec_all() {
    __shared__ bf16 As[2][64][40];
    __shared__ bf16 Bsm[2][128][40];
    int z  = blockIdx.z;
    int b  = z & (BB-1);
    int l  = z >> 2;
    int m0 = blockIdx.y * 64;
    int n0 = blockIdx.x * 128;
    int tid = threadIdx.x;
    int lane = tid & 31, wid = tid >> 5;
    int wm = wid >> 2, wn = wid & 3;
    int g = lane >> 2, tig = lane & 3;
    float acc[2][4][4] = {};
    const bf16* fA = g_fAb[l] + ((size_t)b*CC + m0)*KK;
    const bf16* fB = g_fBb[l] + ((size_t)b*CC + m0)*KK;
    const bf16* BcT = g_BcT + ((size_t)b*NN + n0)*KK;
    const bf16* BsT = g_BsT + ((size_t)b*NN + n0)*KK;
    int arow = tid >> 2, ac8 = (tid & 3) * 8;
    for (int r0 = 0; r0 < KK; r0 += 32) {
        *(uint4*)&As[0][arow][ac8] = *(const uint4*)&fA[(size_t)arow*KK + r0 + ac8];
        *(uint4*)&As[1][arow][ac8] = *(const uint4*)&fB[(size_t)arow*KK + r0 + ac8];
        #pragma unroll
        for (int t = 0; t < 2; t++) {
            int brow = (tid >> 2) + t*64;
            *(uint4*)&Bsm[0][brow][ac8] = *(const uint4*)&BcT[(size_t)brow*KK + r0 + ac8];
            *(uint4*)&Bsm[1][brow][ac8] = *(const uint4*)&BsT[(size_t)brow*KK + r0 + ac8];
        }
        __syncthreads();
        #pragma unroll
        for (int kk = 0; kk < 32; kk += 16) {
            #pragma unroll
            for (int p = 0; p < 2; p++) {
                uint32_t af[2][4];
                #pragma unroll
                for (int ms = 0; ms < 2; ms++) {
                    int m = wm*32 + ms*16;
                    af[ms][0] = *(const uint32_t*)&As[p][m+g  ][kk + 2*tig    ];
                    af[ms][1] = *(const uint32_t*)&As[p][m+g+8][kk + 2*tig    ];
                    af[ms][2] = *(const uint32_t*)&As[p][m+g  ][kk + 2*tig + 8];
                    af[ms][3] = *(const uint32_t*)&As[p][m+g+8][kk + 2*tig + 8];
                }
                #pragma unroll
                for (int ns = 0; ns < 4; ns++) {
                    int n = wn*32 + ns*8;
                    uint32_t bf[2];
                    bf[0] = *(const uint32_t*)&Bsm[p][n+g][kk + 2*tig    ];
                    bf[1] = *(const uint32_t*)&Bsm[p][n+g][kk + 2*tig + 8];
                    #pragma unroll
                    for (int ms = 0; ms < 2; ms++)
                        mma_bf16(acc[ms][ns], af[ms], bf);
                }
            }
        }
        __syncthreads();
    }
    bf16* X1 = g_x1b[l] + (size_t)b*CC*NN;
    #pragma unroll
    for (int ms = 0; ms < 2; ms++) {
        #pragma unroll
        for (int ns = 0; ns < 4; ns++) {
            int m = m0 + wm*32 + ms*16 + g;
            int n = n0 + wn*32 + ns*8 + tig*2;
            *reinterpret_cast<bf162*>(&X1[(size_t)m*NN + n]) =
                __floats2bfloat162_rn(acc[ms][ns][0], acc[ms][ns][1]);
            *reinterpret_cast<bf162*>(&X1[(size_t)(m+8)*NN + n]) =
                __floats2bfloat162_rn(acc[ms][ns][2], acc[ms][ns][3]);
        }
    }
}

// -------- K5b: conv via 3xTF32 + epilogue --------
__global__ void k_conv_tc(const float* __restrict__ convw, int l, int cur) {
    __shared__ float Ah[64][20], Al[64][20];
    __shared__ float Bh[16][132], Bl[16][132];
    int b  = blockIdx.z;
    int m0 = blockIdx.y * 64;
    int n0 = blockIdx.x * 128;
    int tid = threadIdx.x;
    int lane = tid & 31, wid = tid >> 5;
    int wm = wid >> 2, wn = wid & 3;
    int g = lane >> 2, tig = lane & 3;
    float acc[2][4][4] = {};
    const float* W = convw + (size_t)l*CC*CC + (size_t)m0*CC;
    const float* H = g_h[cur] + (size_t)b*CC*NN;
    int arow = tid >> 2, ac4 = (tid & 3) * 4;
    for (int r0 = 0; r0 < CC; r0 += 16) {
        float4 va = *(const float4*)&W[(size_t)arow*CC + r0 + ac4];
        float h0,l0,h1,l1,h2,l2,h3,l3;
        split_tf32(va.x, h0, l0); split_tf32(va.y, h1, l1);
        split_tf32(va.z, h2, l2); split_tf32(va.w, h3, l3);
        Ah[arow][ac4] = h0; Ah[arow][ac4+1] = h1; Ah[arow][ac4+2] = h2; Ah[arow][ac4+3] = h3;
        Al[arow][ac4] = l0; Al[arow][ac4+1] = l1; Al[arow][ac4+2] = l2; Al[arow][ac4+3] = l3;
        #pragma unroll
        for (int t = 0; t < 2; t++) {
            int idx = tid + t*256;
            int brow = idx >> 5, bc4 = (idx & 31) * 4;
            float4 vb = *(const float4*)&H[(size_t)(r0+brow)*NN + n0 + bc4];
            float bh0,bl0,bh1,bl1,bh2,bl2,bh3,bl3;
            split_tf32(vb.x, bh0, bl0); split_tf32(vb.y, bh1, bl1);
            split_tf32(vb.z, bh2, bl2); split_tf32(vb.w, bh3, bl3);
            Bh[brow][bc4] = bh0; Bh[brow][bc4+1] = bh1; Bh[brow][bc4+2] = bh2; Bh[brow][bc4+3] = bh3;
            Bl[brow][bc4] = bl0; Bl[brow][bc4+1] = bl1; Bl[brow][bc4+2] = bl2; Bl[brow][bc4+3] = bl3;
        }
        __syncthreads();
        #pragma unroll
        for (int kk = 0; kk < 16; kk += 8) {
            uint32_t afh[2][4], afl[2][4];
            #pragma unroll
            for (int ms = 0; ms < 2; ms++) {
                int m = wm*32 + ms*16;
                afh[ms][0] = __float_as_uint(Ah[m+g  ][kk+tig  ]);
                afh[ms][1] = __float_as_uint(Ah[m+g+8][kk+tig  ]);
                afh[ms][2] = __float_as_uint(Ah[m+g  ][kk+tig+4]);
                afh[ms][3] = __float_as_uint(Ah[m+g+8][kk+tig+4]);
                afl[ms][0] = __float_as_uint(Al[m+g  ][kk+tig  ]);
                afl[ms][1] = __float_as_uint(Al[m+g+8][kk+tig  ]);
                afl[ms][2] = __float_as_uint(Al[m+g  ][kk+tig+4]);
                afl[ms][3] = __float_as_uint(Al[m+g+8][kk+tig+4]);
            }
            #pragma unroll
            for (int ns = 0; ns < 4; ns++) {
                int n = wn*32 + ns*8;
                uint32_t bfh[2], bfl[2];
                bfh[0] = __float_as_uint(Bh[kk+tig  ][n+g]);
                bfh[1] = __float_as_uint(Bh[kk+tig+4][n+g]);
                bfl[0] = __float_as_uint(Bl[kk+tig  ][n+g]);
                bfl[1] = __float_as_uint(Bl[kk+tig+4][n+g]);
                #pragma unroll
                for (int ms = 0; ms < 2; ms++) {
                    mma_tf32(acc[ms][ns], afh[ms], bfh);
                    mma_tf32(acc[ms][ns], afh[ms], bfl);
                    mma_tf32(acc[ms][ns], afl[ms], bfh);
                }
            }
        }
        __syncthreads();
    }
    int nxt = cur ^ 1;
    const bf16* X1 = g_x1b[l] + (size_t)b*CC*NN;
    float* Hn = g_h[nxt] + (size_t)b*CC*NN;
    #pragma unroll
    for (int ms = 0; ms < 2; ms++) {
        #pragma unroll
        for (int ns = 0; ns < 4; ns++) {
            int m = m0 + wm*32 + ms*16 + g;
            int n = n0 + wn*32 + ns*8 + tig*2;
            float bias0 = g_f0h[l][b*CC + m];
            float bias1 = g_f0h[l][b*CC + m + 8];
            float2 x1a = __bfloat1622float2(*reinterpret_cast<const bf162*>(&X1[(size_t)m*NN + n]));
            float2 x1b = __bfloat1622float2(*reinterpret_cast<const bf162*>(&X1[(size_t)(m+8)*NN + n]));
            float v0 = acc[ms][ns][0] + bias0 + x1a.x;
            float v1 = acc[ms][ns][1] + bias0 + x1a.y;
            float v2 = acc[ms][ns][2] + bias1 + x1b.x;
            float v3 = acc[ms][ns][3] + bias1 + x1b.y;
            if (l < LL - 1) {
                v0 = gelu_exact(v0); v1 = gelu_exact(v1);
                v2 = gelu_exact(v2); v3 = gelu_exact(v3);
            }
            Hn[(size_t)m*NN + n]         = v0;
            Hn[(size_t)m*NN + n + 1]     = v1;
            Hn[(size_t)(m+8)*NN + n]     = v2;
            Hn[(size_t)(m+8)*NN + n + 1] = v3;
        }
    }
}

// -------- K6: head --------
__global__ void k_head(const float* __restrict__ w1, const float* __restrict__ b1,
                       const float* __restrict__ w2, const float* __restrict__ b2,
                       float* __restrict__ out, int cur) {
    __shared__ float sh[CC][32];
    __shared__ float red[CC][33];
    int b  = blockIdx.y;
    int n0 = blockIdx.x * 32;
    int f = threadIdx.x;
    const float* H = g_h[cur] + (size_t)b*CC*NN + n0;
    #pragma unroll 4
    for (int c4 = 0; c4 < CC; c4 += 4) {
        int row = c4 + (f >> 5);
        int col = f & 31;
        sh[row][col] = H[(size_t)row*NN + col];
    }
    __syncthreads();
    float acc[32];
    float bv = b1[f];
    #pragma unroll
    for (int j = 0; j < 32; j++) acc[j] = bv;
    for (int c = 0; c < CC; c++) {
        float w = __ldg(&w1[(size_t)c*FCD + f]);
        #pragma unroll
        for (int j = 0; j < 32; j++) acc[j] += sh[c][j] * w;
    }
    float w2f = __ldg(&w2[f]);
    #pragma unroll
    for (int j = 0; j < 32; j++)
        red[f][j] = gelu_exact(acc[j]) * w2f;
    __syncthreads();
    if (f < 32) {
        float s = b2[0];
        #pragma unroll 8
        for (int q = 0; q < CC; q++) s += red[q][f];
        out[(size_t)b*NN + n0 + f] = s;
    }
}

// -------- launch --------
extern "C" void kernel_launch(void* const* d_in, const int* in_sizes, int n_in,
                              void* d_out, int out_size) {
    (void)in_sizes; (void)n_in; (void)out_size;
    const float* x     = (const float*)d_in[0];
    const float* xf    = (const float*)d_in[1];
    const int*   ind   = (const int*)  d_in[2];
    const float* modes = (const float*)d_in[3];
    const float* fc0_w = (const float*)d_in[4];
    const float* fc0_b = (const float*)d_in[5];
    const float* wc    = (const float*)d_in[6];
    const float* ws    = (const float*)d_in[7];
    const float* w0    = (const float*)d_in[8];
    const float* convw = (const float*)d_in[9];
    const float* convb = (const float*)d_in[10];
    const float* fc1_w = (const float*)d_in[11];
    const float* fc1_b = (const float*)d_in[12];
    const float* fc2_w = (const float*)d_in[13];
    const float* fc2_b = (const float*)d_in[14];
    float* out = (float*)d_out;

    // launch 1
    dim3 g1(NN/32, BB);
    k_basis<<<g1, 256>>>(xf, ind, modes);

    // launch 2
    dim3 g2(NN/256, CC, BB);
    k_fc0<<<g2, 256>>>(x, fc0_w, fc0_b);

    // launch 3
    dim3 g3(KK/64, CC/32, BB*FWD_S);
    k_fwd_tc<<<g3, 256>>>();

    // launch 4 (ncu profiles this one)
    dim3 g4(CC, LL, 2);
    k_mix_all<<<g4, 64>>>(wc, ws);

    // launch 5+
    k_x0h<<<BB*CC, 256>>>();
    k_f0h_all<<<LL, BB*CC>>>(w0, convb);
    dim3 g5(NN/128, CC/64, BB*LL);
    k_inv_spec_all<<<g5, 256>>>();

    int cur = 0;
    for (int l = 0; l < LL; l++) {
        dim3 g6(NN/128, CC/64, BB);
        k_conv_tc<<<g6, 256>>>(convw, l, cur);
        cur ^= 1;
    }

    dim3 g7(NN/32, BB);
    k_head<<<g7, 128>>>(fc1_w, fc1_b, fc2_w, fc2_b, out, cur);
}

// round 11
// speedup vs baseline: 1.0759x; 1.0759x over previous
#include <cuda_runtime.h>
#include <cuda_bf16.h>
#include <math.h>
#include <stdint.h>

#define BB 4
#define NN 4096
#define NFF 8192
#define KK 512
#define CC 128
#define LL 4
#define INDIM 3
#define FCD 128
#define FWD_S 2

typedef __nv_bfloat16 bf16;
typedef __nv_bfloat162 bf162;

// -------- scratch --------
__device__ bf16  g_Bc [BB*KK*NN];      // basis [b][k][n]
__device__ bf16  g_Bs [BB*KK*NN];
__device__ bf16  g_BcT[BB*NN*KK];      // basis [b][n][k]
__device__ bf16  g_BsT[BB*NN*KK];
__device__ float g_wqn[BB*NN];
__device__ float g_h[2][BB*CC*NN];
__device__ bf16  g_hwb[BB*CC*NN];      // h0*wqn bf16
__device__ float g_pc[FWD_S][BB*CC*KK];  // forward partials
__device__ float g_ps[FWD_S][BB*CC*KK];
__device__ bf16  g_xck[CC*KK*BB];      // combined fwd coeffs, packed [i][k][b]
__device__ bf16  g_xsk[CC*KK*BB];
__device__ bf16  g_fAb[LL][BB*CC*KK];
__device__ bf16  g_fBb[LL][BB*CC*KK];
__device__ bf16  g_x1b[LL][BB*CC*NN];  // spectral inverse, bf16
__device__ float g_x0h[BB*CC];
__device__ float g_f0h[LL][BB*CC];

__device__ __forceinline__ float gelu_exact(float v) {
    return 0.5f * v * (1.0f + erff(v * 0.7071067811865476f));
}
__device__ __forceinline__ float tf32r(float x) {
    float r;
    asm("cvt.rna.tf32.f32 %0, %1;" : "=f"(r) : "f"(x));
    return r;
}
__device__ __forceinline__ void split_tf32(float v, float& hi, float& lo) {
    hi = tf32r(v);
    lo = tf32r(v - hi);
}
__device__ __forceinline__ void mma_tf32(float (&d)[4], const uint32_t (&a)[4],
                                         const uint32_t (&b)[2]) {
    asm volatile(
        "mma.sync.aligned.m16n8k8.row.col.f32.tf32.tf32.f32 "
        "{%0,%1,%2,%3}, {%4,%5,%6,%7}, {%8,%9}, {%0,%1,%2,%3};"
        : "+f"(d[0]), "+f"(d[1]), "+f"(d[2]), "+f"(d[3])
        : "r"(a[0]), "r"(a[1]), "r"(a[2]), "r"(a[3]), "r"(b[0]), "r"(b[1]));
}
__device__ __forceinline__ void mma_bf16(float (&d)[4], const uint32_t (&a)[4],
                                         const uint32_t (&b)[2]) {
    asm volatile(
        "mma.sync.aligned.m16n8k16.row.col.f32.bf16.bf16.f32 "
        "{%0,%1,%2,%3}, {%4,%5,%6,%7}, {%8,%9}, {%0,%1,%2,%3};"
        : "+f"(d[0]), "+f"(d[1]), "+f"(d[2]), "+f"(d[3])
        : "r"(a[0]), "r"(a[1]), "r"(a[2]), "r"(a[3]), "r"(b[0]), "r"(b[1]));
}

// -------- K1: basis via integer-mode angle addition + fused wqn --------
__global__ void k_basis(const float* __restrict__ xf, const int* __restrict__ ind,
                        const float* __restrict__ modes) {
    __shared__ float txC[33][32], txS[33][32], tyC[33][32], tyS[33][32];
    __shared__ bf16 tc[32][34], ts[32][34];
    int b  = blockIdx.y;
    int n0 = blockIdx.x * 32;
    int tid = threadIdx.x;
    int tx = tid & 31;
    int ty = tid >> 5;
    if (ty == 0) {
        int n = n0 + tx;
        int f = __ldg(&ind[n]);
        const float* xfp = xf + ((size_t)b*NFF + f)*4;
        float gx = __ldg(&xfp[0]);
        float gy = __ldg(&xfp[1]);
        g_wqn[b*NN + n] = __ldg(&xfp[2]) * (float)NN;
        float c1, s1;
        sincosf(gx, &s1, &c1);
        txC[16][tx] = 1.f; txS[16][tx] = 0.f;
        float cj = c1, sj = s1;
        #pragma unroll
        for (int j = 1; j <= 16; j++) {
            txC[16+j][tx] = cj;  txS[16+j][tx] = sj;
            txC[16-j][tx] = cj;  txS[16-j][tx] = -sj;
            float cn = cj*c1 - sj*s1;
            float sn = sj*c1 + cj*s1;
            cj = cn; sj = sn;
        }
        sincosf(gy, &s1, &c1);
        tyC[16][tx] = 1.f; tyS[16][tx] = 0.f;
        cj = c1; sj = s1;
        #pragma unroll
        for (int j = 1; j <= 16; j++) {
            tyC[16+j][tx] = cj;  tyS[16+j][tx] = sj;
            tyC[16-j][tx] = cj;  tyS[16-j][tx] = -sj;
            float cn = cj*c1 - sj*s1;
            float sn = sj*c1 + cj*s1;
            cj = cn; sj = sn;
        }
    }
    __syncthreads();
    for (int k0 = 0; k0 < KK; k0 += 32) {
        #pragma unroll
        for (int jj = 0; jj < 4; jj++) {
            int kr = ty*4 + jj;
            int k = k0 + kr;
            int jx = (int)__ldg(&modes[2*k])   + 16;
            int jy = (int)__ldg(&modes[2*k+1]) + 16;
            float ca = txC[jx][tx], sa = txS[jx][tx];
            float cb = tyC[jy][tx], sb = tyS[jy][tx];
            float c = ca*cb - sa*sb;
            float s = sa*cb + ca*sb;
            bf16 cb16 = __float2bfloat16(c);
            bf16 sb16 = __float2bfloat16(s);
            tc[kr][tx] = cb16;
            ts[kr][tx] = sb16;
            g_Bc[((size_t)b*KK + k)*NN + n0 + tx] = cb16;
            g_Bs[((size_t)b*KK + k)*NN + n0 + tx] = sb16;
        }
        __syncthreads();
        #pragma unroll
        for (int jj = 0; jj < 4; jj++) {
            int nr = ty*4 + jj;
            int n = n0 + nr;
            g_BcT[((size_t)b*NN + n)*KK + k0 + tx] = tc[tx][nr];
            g_BsT[((size_t)b*NN + n)*KK + k0 + tx] = ts[tx][nr];
        }
        __syncthreads();
    }
}

// -------- K2: fc0 --------
__global__ void k_fc0(const float* __restrict__ x, const float* __restrict__ w,
                      const float* __restrict__ bias) {
    int n = blockIdx.x * blockDim.x + threadIdx.x;
    int c = blockIdx.y;
    int b = blockIdx.z;
    const float* xp = x + ((size_t)b * NN + n) * INDIM;
    float acc = bias[c]
              + xp[0] * w[0*CC + c]
              + xp[1] * w[1*CC + c]
              + xp[2] * w[2*CC + c];
    size_t o = ((size_t)b*CC + c) * NN + n;
    g_h[0][o] = acc;
    g_hwb[o]  = __float2bfloat16(acc * g_wqn[b*NN + n]);
}

// -------- K2b: x0h --------
__global__ void k_x0h() {
    int bc = blockIdx.x;
    const bf162* p = reinterpret_cast<const bf162*>(g_hwb + (size_t)bc * NN);
    float acc = 0.f;
    for (int n = threadIdx.x; n < NN/2; n += 256) {
        float2 v = __bfloat1622float2(p[n]);
        acc += v.x + v.y;
    }
    __shared__ float red[256];
    red[threadIdx.x] = acc;
    __syncthreads();
    for (int s = 128; s > 0; s >>= 1) {
        if (threadIdx.x < s) red[threadIdx.x] += red[threadIdx.x + s];
        __syncthreads();
    }
    if (threadIdx.x == 0) g_x0h[bc] = red[0];
}

// -------- K3: forward dual GEMM, bf16 TC, split-N --------
__global__ void k_fwd_tc() {
    __shared__ bf16 As[32][72];
    __shared__ bf16 Bsm[2][64][72];
    int z   = blockIdx.z;
    int b   = z >> 1;
    int s   = z & 1;
    int m0  = blockIdx.y * 32;
    int ko0 = blockIdx.x * 64;
    int tid = threadIdx.x;
    int lane = tid & 31, wid = tid >> 5;
    int wm = wid >> 2, wn = wid & 3;
    int g = lane >> 2, tig = lane & 3;
    float acc[2][2][4] = {};
    const bf16* A  = g_hwb + ((size_t)b*CC + m0) * NN + s * (NN/FWD_S);
    const bf16* Bc = g_Bc  + ((size_t)b*KK + ko0) * NN + s * (NN/FWD_S);
    const bf16* Bs = g_Bs  + ((size_t)b*KK + ko0) * NN + s * (NN/FWD_S);
    int arow = tid >> 3, ac8 = (tid & 7) * 8;
    for (int r0 = 0; r0 < NN/FWD_S; r0 += 64) {
        *(uint4*)&As[arow][ac8] = *(const uint4*)&A[(size_t)arow*NN + r0 + ac8];
        #pragma unroll
        for (int t = 0; t < 2; t++) {
            int brow = (tid >> 3) + t*32;
            *(uint4*)&Bsm[0][brow][ac8] = *(const uint4*)&Bc[(size_t)brow*NN + r0 + ac8];
            *(uint4*)&Bsm[1][brow][ac8] = *(const uint4*)&Bs[(size_t)brow*NN + r0 + ac8];
        }
        __syncthreads();
        #pragma unroll
        for (int kk = 0; kk < 64; kk += 16) {
            uint32_t af[4];
            int m = wm * 16;
            af[0] = *(const uint32_t*)&As[m+g  ][kk + 2*tig    ];
            af[1] = *(const uint32_t*)&As[m+g+8][kk + 2*tig    ];
            af[2] = *(const uint32_t*)&As[m+g  ][kk + 2*tig + 8];
            af[3] = *(const uint32_t*)&As[m+g+8][kk + 2*tig + 8];
            #pragma unroll
            for (int p = 0; p < 2; p++) {
                #pragma unroll
                for (int ns = 0; ns < 2; ns++) {
                    int n = wn * 16 + ns * 8;
                    uint32_t bf[2];
                    bf[0] = *(const uint32_t*)&Bsm[p][n+g][kk + 2*tig    ];
                    bf[1] = *(const uint32_t*)&Bsm[p][n+g][kk + 2*tig + 8];
                    mma_bf16(acc[p][ns], af, bf);
                }
            }
        }
        __syncthreads();
    }
    #pragma unroll
    for (int ns = 0; ns < 2; ns++) {
        int m = m0 + wm*16 + g;
        int k = ko0 + wn*16 + ns*8 + tig*2;
        size_t o0 = ((size_t)b*CC + m)*KK + k;
        size_t o1 = ((size_t)b*CC + m + 8)*KK + k;
        g_pc[s][o0]   = acc[0][ns][0];
        g_pc[s][o0+1] = acc[0][ns][1];
        g_pc[s][o1]   = acc[0][ns][2];
        g_pc[s][o1+1] = acc[0][ns][3];
        g_ps[s][o0]   = acc[1][ns][0];
        g_ps[s][o0+1] = acc[1][ns][1];
        g_ps[s][o1]   = acc[1][ns][2];
        g_ps[s][o1+1] = acc[1][ns][3];
    }
}

// -------- K3b: combine fwd partials -> packed bf16 [i][k][b] --------
__global__ void k_comb() {
    int idx = blockIdx.x * 256 + threadIdx.x;   // i*KK + k, 64K total
    int i = idx >> 9;
    int k = idx & (KK - 1);
    bf16 outc[BB], outs[BB];
    #pragma unroll
    for (int b = 0; b < BB; b++) {
        size_t o = ((size_t)b*CC + i)*KK + k;
        outc[b] = __float2bfloat16(g_pc[0][o] + g_pc[1][o]);
        outs[b] = __float2bfloat16(g_ps[0][o] + g_ps[1][o]);
    }
    *(uint64_t*)&g_xck[(size_t)idx*BB] = *(uint64_t*)outc;
    *(uint64_t*)&g_xsk[(size_t)idx*BB] = *(uint64_t*)outs;
}

// -------- K4: mode mix — 6 wide loads per i (2 weights + packed coeffs) --------
__global__ void k_mix_all(const float* __restrict__ wc, const float* __restrict__ ws) {
    int o  = blockIdx.x;
    int l  = blockIdx.y;
    int k0 = threadIdx.x * 4;
    const float inv_nf = 1.0f / (float)NFF;
    float accc[4][BB] = {};   // [k][b]
    float accs[4][BB] = {};
    const float* wcp = wc + (((size_t)l*CC)*CC + o)*KK + k0;
    const float* wsp = ws + (((size_t)l*CC)*CC + o)*KK + k0;
    #pragma unroll 4
    for (int i = 0; i < CC; i++) {
        float4 wcv = *(const float4*)(wcp + (size_t)i*CC*KK);
        float4 wsv = *(const float4*)(wsp + (size_t)i*CC*KK);
        float wcs[4] = {wcv.x, wcv.y, wcv.z, wcv.w};
        float wss[4] = {wsv.x, wsv.y, wsv.z, wsv.w};
        const bf162* xcp = (const bf162*)&g_xck[((size_t)i*KK + k0)*BB];
        const bf162* xsp2 = (const bf162*)&g_xsk[((size_t)i*KK + k0)*BB];
        #pragma unroll
        for (int kk = 0; kk < 4; kk++) {
            float2 c01 = __bfloat1622float2(xcp[kk*2]);
            float2 c23 = __bfloat1622float2(xcp[kk*2+1]);
            float2 s01 = __bfloat1622float2(xsp2[kk*2]);
            float2 s23 = __bfloat1622float2(xsp2[kk*2+1]);
            float xc[4] = {c01.x, c01.y, c23.x, c23.y};
            float xs[4] = {s01.x, s01.y, s23.x, s23.y};
            #pragma unroll
            for (int b = 0; b < BB; b++) {
                accc[kk][b] += xc[b]*wcs[kk] + xs[b]*wss[kk];
                accs[kk][b] += xc[b]*wss[kk] - xs[b]*wcs[kk];
            }
        }
    }
    #pragma unroll
    for (int b = 0; b < BB; b++) {
        size_t o4 = ((size_t)b*CC + o)*KK + k0;
        bf162* fa = reinterpret_cast<bf162*>(&g_fAb[l][o4]);
        bf162* fb = reinterpret_cast<bf162*>(&g_fBb[l][o4]);
        fa[0] = __floats2bfloat162_rn( 2.0f*inv_nf*accc[0][b],  2.0f*inv_nf*accc[1][b]);
        fa[1] = __floats2bfloat162_rn( 2.0f*inv_nf*accc[2][b],  2.0f*inv_nf*accc[3][b]);
        fb[0] = __floats2bfloat162_rn(-2.0f*inv_nf*accs[0][b], -2.0f*inv_nf*accs[1][b]);
        fb[1] = __floats2bfloat162_rn(-2.0f*inv_nf*accs[2][b], -2.0f*inv_nf*accs[3][b]);
    }
}

// -------- K4b: f0h --------
__global__ void k_f0h_all(const float* __restrict__ w0, const float* __restrict__ convb) {
    int l = blockIdx.x;
    int t = threadIdx.x;
    int b = t >> 7, o = t & 127;
    float acc = 0.f;
    #pragma unroll 4
    for (int i = 0; i < CC; i++)
        acc += g_x0h[b*CC + i] * __ldg(&w0[((size_t)l*CC + i)*CC + o]);
    g_f0h[l][t] = acc * (1.0f / (float)NFF) + convb[l*CC + o];
}

// -------- K5a: inverse spectral GEMM --------
__global__ void k_inv_spec_all() {
    __shared__ bf16 As[2][64][40];
    __shared__ bf16 Bsm[2][128][40];
    int z  = blockIdx.z;
    int b  = z & (BB-1);
    int l  = z >> 2;
    int m0 = blockIdx.y * 64;
    int n0 = blockIdx.x * 128;
    int tid = threadIdx.x;
    int lane = tid & 31, wid = tid >> 5;
    int wm = wid >> 2, wn = wid & 3;
    int g = lane >> 2, tig = lane & 3;
    float acc[2][4][4] = {};
    const bf16* fA = g_fAb[l] + ((size_t)b*CC + m0)*KK;
    const bf16* fB = g_fBb[l] + ((size_t)b*CC + m0)*KK;
    const bf16* BcT = g_BcT + ((size_t)b*NN + n0)*KK;
    const bf16* BsT = g_BsT + ((size_t)b*NN + n0)*KK;
    int arow = tid >> 2, ac8 = (tid & 3) * 8;
    for (int r0 = 0; r0 < KK; r0 += 32) {
        *(uint4*)&As[0][arow][ac8] = *(const uint4*)&fA[(size_t)arow*KK + r0 + ac8];
        *(uint4*)&As[1][arow][ac8] = *(const uint4*)&fB[(size_t)arow*KK + r0 + ac8];
        #pragma unroll
        for (int t = 0; t < 2; t++) {
            int brow = (tid >> 2) + t*64;
            *(uint4*)&Bsm[0][brow][ac8] = *(const uint4*)&BcT[(size_t)brow*KK + r0 + ac8];
            *(uint4*)&Bsm[1][brow][ac8] = *(const uint4*)&BsT[(size_t)brow*KK + r0 + ac8];
        }
        __syncthreads();
        #pragma unroll
        for (int kk = 0; kk < 32; kk += 16) {
            #pragma unroll
            for (int p = 0; p < 2; p++) {
                uint32_t af[2][4];
                #pragma unroll
                for (int ms = 0; ms < 2; ms++) {
                    int m = wm*32 + ms*16;
                    af[ms][0] = *(const uint32_t*)&As[p][m+g  ][kk + 2*tig    ];
                    af[ms][1] = *(const uint32_t*)&As[p][m+g+8][kk + 2*tig    ];
                    af[ms][2] = *(const uint32_t*)&As[p][m+g  ][kk + 2*tig + 8];
                    af[ms][3] = *(const uint32_t*)&As[p][m+g+8][kk + 2*tig + 8];
                }
                #pragma unroll
                for (int ns = 0; ns < 4; ns++) {
                    int n = wn*32 + ns*8;
                    uint32_t bf[2];
                    bf[0] = *(const uint32_t*)&Bsm[p][n+g][kk + 2*tig    ];
                    bf[1] = *(const uint32_t*)&Bsm[p][n+g][kk + 2*tig + 8];
                    #pragma unroll
                    for (int ms = 0; ms < 2; ms++)
                        mma_bf16(acc[ms][ns], af[ms], bf);
                }
            }
        }
        __syncthreads();
    }
    bf16* X1 = g_x1b[l] + (size_t)b*CC*NN;
    #pragma unroll
    for (int ms = 0; ms < 2; ms++) {
        #pragma unroll
        for (int ns = 0; ns < 4; ns++) {
            int m = m0 + wm*32 + ms*16 + g;
            int n = n0 + wn*32 + ns*8 + tig*2;
            *reinterpret_cast<bf162*>(&X1[(size_t)m*NN + n]) =
                __floats2bfloat162_rn(acc[ms][ns][0], acc[ms][ns][1]);
            *reinterpret_cast<bf162*>(&X1[(size_t)(m+8)*NN + n]) =
                __floats2bfloat162_rn(acc[ms][ns][2], acc[ms][ns][3]);
        }
    }
}

// -------- K5b: conv via 3xTF32 + epilogue --------
__global__ void k_conv_tc(const float* __restrict__ convw, int l, int cur) {
    __shared__ float Ah[64][20], Al[64][20];
    __shared__ float Bh[16][132], Bl[16][132];
    int b  = blockIdx.z;
    int m0 = blockIdx.y * 64;
    int n0 = blockIdx.x * 128;
    int tid = threadIdx.x;
    int lane = tid & 31, wid = tid >> 5;
    int wm = wid >> 2, wn = wid & 3;
    int g = lane >> 2, tig = lane & 3;
    float acc[2][4][4] = {};
    const float* W = convw + (size_t)l*CC*CC + (size_t)m0*CC;
    const float* H = g_h[cur] + (size_t)b*CC*NN;
    int arow = tid >> 2, ac4 = (tid & 3) * 4;
    for (int r0 = 0; r0 < CC; r0 += 16) {
        float4 va = *(const float4*)&W[(size_t)arow*CC + r0 + ac4];
        float h0,l0,h1,l1,h2,l2,h3,l3;
        split_tf32(va.x, h0, l0); split_tf32(va.y, h1, l1);
        split_tf32(va.z, h2, l2); split_tf32(va.w, h3, l3);
        Ah[arow][ac4] = h0; Ah[arow][ac4+1] = h1; Ah[arow][ac4+2] = h2; Ah[arow][ac4+3] = h3;
        Al[arow][ac4] = l0; Al[arow][ac4+1] = l1; Al[arow][ac4+2] = l2; Al[arow][ac4+3] = l3;
        #pragma unroll
        for (int t = 0; t < 2; t++) {
            int idx = tid + t*256;
            int brow = idx >> 5, bc4 = (idx & 31) * 4;
            float4 vb = *(const float4*)&H[(size_t)(r0+brow)*NN + n0 + bc4];
            float bh0,bl0,bh1,bl1,bh2,bl2,bh3,bl3;
            split_tf32(vb.x, bh0, bl0); split_tf32(vb.y, bh1, bl1);
            split_tf32(vb.z, bh2, bl2); split_tf32(vb.w, bh3, bl3);
            Bh[brow][bc4] = bh0; Bh[brow][bc4+1] = bh1; Bh[brow][bc4+2] = bh2; Bh[brow][bc4+3] = bh3;
            Bl[brow][bc4] = bl0; Bl[brow][bc4+1] = bl1; Bl[brow][bc4+2] = bl2; Bl[brow][bc4+3] = bl3;
        }
        __syncthreads();
        #pragma unroll
        for (int kk = 0; kk < 16; kk += 8) {
            uint32_t afh[2][4], afl[2][4];
            #pragma unroll
            for (int ms = 0; ms < 2; ms++) {
                int m = wm*32 + ms*16;
                afh[ms][0] = __float_as_uint(Ah[m+g  ][kk+tig  ]);
                afh[ms][1] = __float_as_uint(Ah[m+g+8][kk+tig  ]);
                afh[ms][2] = __float_as_uint(Ah[m+g  ][kk+tig+4]);
                afh[ms][3] = __float_as_uint(Ah[m+g+8][kk+tig+4]);
                afl[ms][0] = __float_as_uint(Al[m+g  ][kk+tig  ]);
                afl[ms][1] = __float_as_uint(Al[m+g+8][kk+tig  ]);
                afl[ms][2] = __float_as_uint(Al[m+g  ][kk+tig+4]);
                afl[ms][3] = __float_as_uint(Al[m+g+8][kk+tig+4]);
            }
            #pragma unroll
            for (int ns = 0; ns < 4; ns++) {
                int n = wn*32 + ns*8;
                uint32_t bfh[2], bfl[2];
                bfh[0] = __float_as_uint(Bh[kk+tig  ][n+g]);
                bfh[1] = __float_as_uint(Bh[kk+tig+4][n+g]);
                bfl[0] = __float_as_uint(Bl[kk+tig  ][n+g]);
                bfl[1] = __float_as_uint(Bl[kk+tig+4][n+g]);
                #pragma unroll
                for (int ms = 0; ms < 2; ms++) {
                    mma_tf32(acc[ms][ns], afh[ms], bfh);
                    mma_tf32(acc[ms][ns], afh[ms], bfl);
                    mma_tf32(acc[ms][ns], afl[ms], bfh);
                }
            }
        }
        __syncthreads();
    }
    int nxt = cur ^ 1;
    const bf16* X1 = g_x1b[l] + (size_t)b*CC*NN;
    float* Hn = g_h[nxt] + (size_t)b*CC*NN;
    #pragma unroll
    for (int ms = 0; ms < 2; ms++) {
        #pragma unroll
        for (int ns = 0; ns < 4; ns++) {
            int m = m0 + wm*32 + ms*16 + g;
            int n = n0 + wn*32 + ns*8 + tig*2;
            float bias0 = g_f0h[l][b*CC + m];
            float bias1 = g_f0h[l][b*CC + m + 8];
            float2 x1a = __bfloat1622float2(*reinterpret_cast<const bf162*>(&X1[(size_t)m*NN + n]));
            float2 x1b = __bfloat1622float2(*reinterpret_cast<const bf162*>(&X1[(size_t)(m+8)*NN + n]));
            float v0 = acc[ms][ns][0] + bias0 + x1a.x;
            float v1 = acc[ms][ns][1] + bias0 + x1a.y;
            float v2 = acc[ms][ns][2] + bias1 + x1b.x;
            float v3 = acc[ms][ns][3] + bias1 + x1b.y;
            if (l < LL - 1) {
                v0 = gelu_exact(v0); v1 = gelu_exact(v1);
                v2 = gelu_exact(v2); v3 = gelu_exact(v3);
            }
            Hn[(size_t)m*NN + n]         = v0;
            Hn[(size_t)m*NN + n + 1]     = v1;
            Hn[(size_t)(m+8)*NN + n]     = v2;
            Hn[(size_t)(m+8)*NN + n + 1] = v3;
        }
    }
}

// -------- K6: head --------
__global__ void k_head(const float* __restrict__ w1, const float* __restrict__ b1,
                       const float* __restrict__ w2, const float* __restrict__ b2,
                       float* __restrict__ out, int cur) {
    __shared__ float sh[CC][32];
    __shared__ float red[CC][33];
    int b  = blockIdx.y;
    int n0 = blockIdx.x * 32;
    int f = threadIdx.x;
    const float* H = g_h[cur] + (size_t)b*CC*NN + n0;
    #pragma unroll 4
    for (int c4 = 0; c4 < CC; c4 += 4) {
        int row = c4 + (f >> 5);
        int col = f & 31;
        sh[row][col] = H[(size_t)row*NN + col];
    }
    __syncthreads();
    float acc[32];
    float bv = b1[f];
    #pragma unroll
    for (int j = 0; j < 32; j++) acc[j] = bv;
    for (int c = 0; c < CC; c++) {
        float w = __ldg(&w1[(size_t)c*FCD + f]);
        #pragma unroll
        for (int j = 0; j < 32; j++) acc[j] += sh[c][j] * w;
    }
    float w2f = __ldg(&w2[f]);
    #pragma unroll
    for (int j = 0; j < 32; j++)
        red[f][j] = gelu_exact(acc[j]) * w2f;
    __syncthreads();
    if (f < 32) {
        float s = b2[0];
        #pragma unroll 8
        for (int q = 0; q < CC; q++) s += red[q][f];
        out[(size_t)b*NN + n0 + f] = s;
    }
}

// -------- launch --------
extern "C" void kernel_launch(void* const* d_in, const int* in_sizes, int n_in,
                              void* d_out, int out_size) {
    (void)in_sizes; (void)n_in; (void)out_size;
    const float* x     = (const float*)d_in[0];
    const float* xf    = (const float*)d_in[1];
    const int*   ind   = (const int*)  d_in[2];
    const float* modes = (const float*)d_in[3];
    const float* fc0_w = (const float*)d_in[4];
    const float* fc0_b = (const float*)d_in[5];
    const float* wc    = (const float*)d_in[6];
    const float* ws    = (const float*)d_in[7];
    const float* w0    = (const float*)d_in[8];
    const float* convw = (const float*)d_in[9];
    const float* convb = (const float*)d_in[10];
    const float* fc1_w = (const float*)d_in[11];
    const float* fc1_b = (const float*)d_in[12];
    const float* fc2_w = (const float*)d_in[13];
    const float* fc2_b = (const float*)d_in[14];
    float* out = (float*)d_out;

    // launch 1
    dim3 g1(NN/32, BB);
    k_basis<<<g1, 256>>>(xf, ind, modes);
    // launch 2
    dim3 g2(NN/256, CC, BB);
    k_fc0<<<g2, 256>>>(x, fc0_w, fc0_b);
    // launch 3: forward GEMM + combine into packed bf16
    dim3 g3(KK/64, CC/32, BB*FWD_S);
    k_fwd_tc<<<g3, 256>>>();
    k_comb<<<CC*KK/256, 256>>>();   // launch 4? no — keep mix at slot 4... comb is 4th

    // NOTE: ncu profiles the 4th launch = k_comb is tiny; swap order so mix is 4th:
    // (comb must precede mix; put comb 4th is wasteful. Keep mix 5th and accept it,
    //  or fold x0h earlier. We place mix 5th; profile slot will show k_comb->mix next.)

    // launch 5: the big weight stream
    dim3 g4(CC, LL);
    k_mix_all<<<g4, 128>>>(wc, ws);

    k_x0h<<<BB*CC, 256>>>();
    k_f0h_all<<<LL, BB*CC>>>(w0, convb);
    dim3 g5(NN/128, CC/64, BB*LL);
    k_inv_spec_all<<<g5, 256>>>();

    int cur = 0;
    for (int l = 0; l < LL; l++) {
        dim3 g6(NN/128, CC/64, BB);
        k_conv_tc<<<g6, 256>>>(convw, l, cur);
        cur ^= 1;
    }

    dim3 g7(NN/32, BB);
    k_head<<<g7, 128>>>(fc1_w, fc1_b, fc2_w, fc2_b, out, cur);
}

// round 12
// speedup vs baseline: 1.2085x; 1.1233x over previous
#include <cuda_runtime.h>
#include <cuda_bf16.h>
#include <math.h>
#include <stdint.h>

#define BB 4
#define NN 4096
#define NFF 8192
#define KK 512
#define CC 128
#define LL 4
#define INDIM 3
#define FCD 128
#define FWD_S 2

typedef __nv_bfloat16 bf16;
typedef __nv_bfloat162 bf162;

// -------- scratch --------
__device__ bf16  g_Bc [BB*KK*NN];      // basis [b][k][n]
__device__ bf16  g_Bs [BB*KK*NN];
__device__ bf16  g_BcT[BB*NN*KK];      // basis [b][n][k]
__device__ bf16  g_BsT[BB*NN*KK];
__device__ float g_wqn[BB*NN];
__device__ float g_h[2][BB*CC*NN];
__device__ bf16  g_hwb[BB*CC*NN];      // h0*wqn bf16
__device__ float g_pc[FWD_S][BB*CC*KK];  // forward partials
__device__ float g_ps[FWD_S][BB*CC*KK];
__device__ bf16  g_xck[CC*KK*BB];      // combined fwd coeffs, packed [i][k][b]
__device__ bf16  g_xsk[CC*KK*BB];
__device__ bf16  g_fAb[LL][BB*CC*KK];
__device__ bf16  g_fBb[LL][BB*CC*KK];
__device__ bf16  g_x1b[LL][BB*CC*NN];  // spectral inverse, bf16
__device__ float g_x0h[BB*CC];
__device__ float g_f0h[LL][BB*CC];

__device__ __forceinline__ float gelu_exact(float v) {
    return 0.5f * v * (1.0f + erff(v * 0.7071067811865476f));
}
__device__ __forceinline__ float tf32r(float x) {
    float r;
    asm("cvt.rna.tf32.f32 %0, %1;" : "=f"(r) : "f"(x));
    return r;
}
__device__ __forceinline__ void split_tf32(float v, float& hi, float& lo) {
    hi = tf32r(v);
    lo = tf32r(v - hi);
}
__device__ __forceinline__ void mma_tf32(float (&d)[4], const uint32_t (&a)[4],
                                         const uint32_t (&b)[2]) {
    asm volatile(
        "mma.sync.aligned.m16n8k8.row.col.f32.tf32.tf32.f32 "
        "{%0,%1,%2,%3}, {%4,%5,%6,%7}, {%8,%9}, {%0,%1,%2,%3};"
        : "+f"(d[0]), "+f"(d[1]), "+f"(d[2]), "+f"(d[3])
        : "r"(a[0]), "r"(a[1]), "r"(a[2]), "r"(a[3]), "r"(b[0]), "r"(b[1]));
}
__device__ __forceinline__ void mma_bf16(float (&d)[4], const uint32_t (&a)[4],
                                         const uint32_t (&b)[2]) {
    asm volatile(
        "mma.sync.aligned.m16n8k16.row.col.f32.bf16.bf16.f32 "
        "{%0,%1,%2,%3}, {%4,%5,%6,%7}, {%8,%9}, {%0,%1,%2,%3};"
        : "+f"(d[0]), "+f"(d[1]), "+f"(d[2]), "+f"(d[3])
        : "r"(a[0]), "r"(a[1]), "r"(a[2]), "r"(a[3]), "r"(b[0]), "r"(b[1]));
}

// -------- K1: basis via integer-mode angle addition + fused wqn --------
__global__ void k_basis(const float* __restrict__ xf, const int* __restrict__ ind,
                        const float* __restrict__ modes) {
    __shared__ float txC[33][32], txS[33][32], tyC[33][32], tyS[33][32];
    __shared__ bf16 tc[32][34], ts[32][34];
    int b  = blockIdx.y;
    int n0 = blockIdx.x * 32;
    int tid = threadIdx.x;
    int tx = tid & 31;
    int ty = tid >> 5;
    if (ty == 0) {
        int n = n0 + tx;
        int f = __ldg(&ind[n]);
        const float* xfp = xf + ((size_t)b*NFF + f)*4;
        float gx = __ldg(&xfp[0]);
        float gy = __ldg(&xfp[1]);
        g_wqn[b*NN + n] = __ldg(&xfp[2]) * (float)NN;
        float c1, s1;
        sincosf(gx, &s1, &c1);
        txC[16][tx] = 1.f; txS[16][tx] = 0.f;
        float cj = c1, sj = s1;
        #pragma unroll
        for (int j = 1; j <= 16; j++) {
            txC[16+j][tx] = cj;  txS[16+j][tx] = sj;
            txC[16-j][tx] = cj;  txS[16-j][tx] = -sj;
            float cn = cj*c1 - sj*s1;
            float sn = sj*c1 + cj*s1;
            cj = cn; sj = sn;
        }
        sincosf(gy, &s1, &c1);
        tyC[16][tx] = 1.f; tyS[16][tx] = 0.f;
        cj = c1; sj = s1;
        #pragma unroll
        for (int j = 1; j <= 16; j++) {
            tyC[16+j][tx] = cj;  tyS[16+j][tx] = sj;
            tyC[16-j][tx] = cj;  tyS[16-j][tx] = -sj;
            float cn = cj*c1 - sj*s1;
            float sn = sj*c1 + cj*s1;
            cj = cn; sj = sn;
        }
    }
    __syncthreads();
    for (int k0 = 0; k0 < KK; k0 += 32) {
        #pragma unroll
        for (int jj = 0; jj < 4; jj++) {
            int kr = ty*4 + jj;
            int k = k0 + kr;
            int jx = (int)__ldg(&modes[2*k])   + 16;
            int jy = (int)__ldg(&modes[2*k+1]) + 16;
            float ca = txC[jx][tx], sa = txS[jx][tx];
            float cb = tyC[jy][tx], sb = tyS[jy][tx];
            float c = ca*cb - sa*sb;
            float s = sa*cb + ca*sb;
            bf16 cb16 = __float2bfloat16(c);
            bf16 sb16 = __float2bfloat16(s);
            tc[kr][tx] = cb16;
            ts[kr][tx] = sb16;
            g_Bc[((size_t)b*KK + k)*NN + n0 + tx] = cb16;
            g_Bs[((size_t)b*KK + k)*NN + n0 + tx] = sb16;
        }
        __syncthreads();
        #pragma unroll
        for (int jj = 0; jj < 4; jj++) {
            int nr = ty*4 + jj;
            int n = n0 + nr;
            g_BcT[((size_t)b*NN + n)*KK + k0 + tx] = tc[tx][nr];
            g_BsT[((size_t)b*NN + n)*KK + k0 + tx] = ts[tx][nr];
        }
        __syncthreads();
    }
}

// -------- K2: fc0 --------
__global__ void k_fc0(const float* __restrict__ x, const float* __restrict__ w,
                      const float* __restrict__ bias) {
    int n = blockIdx.x * blockDim.x + threadIdx.x;
    int c = blockIdx.y;
    int b = blockIdx.z;
    const float* xp = x + ((size_t)b * NN + n) * INDIM;
    float acc = bias[c]
              + xp[0] * w[0*CC + c]
              + xp[1] * w[1*CC + c]
              + xp[2] * w[2*CC + c];
    size_t o = ((size_t)b*CC + c) * NN + n;
    g_h[0][o] = acc;
    g_hwb[o]  = __float2bfloat16(acc * g_wqn[b*NN + n]);
}

// -------- K2b: x0h --------
__global__ void k_x0h() {
    int bc = blockIdx.x;
    const bf162* p = reinterpret_cast<const bf162*>(g_hwb + (size_t)bc * NN);
    float acc = 0.f;
    for (int n = threadIdx.x; n < NN/2; n += 256) {
        float2 v = __bfloat1622float2(p[n]);
        acc += v.x + v.y;
    }
    __shared__ float red[256];
    red[threadIdx.x] = acc;
    __syncthreads();
    for (int s = 128; s > 0; s >>= 1) {
        if (threadIdx.x < s) red[threadIdx.x] += red[threadIdx.x + s];
        __syncthreads();
    }
    if (threadIdx.x == 0) g_x0h[bc] = red[0];
}

// -------- K3: forward dual GEMM, bf16 TC, split-N --------
__global__ void k_fwd_tc() {
    __shared__ bf16 As[32][72];
    __shared__ bf16 Bsm[2][64][72];
    int z   = blockIdx.z;
    int b   = z >> 1;
    int s   = z & 1;
    int m0  = blockIdx.y * 32;
    int ko0 = blockIdx.x * 64;
    int tid = threadIdx.x;
    int lane = tid & 31, wid = tid >> 5;
    int wm = wid >> 2, wn = wid & 3;
    int g = lane >> 2, tig = lane & 3;
    float acc[2][2][4] = {};
    const bf16* A  = g_hwb + ((size_t)b*CC + m0) * NN + s * (NN/FWD_S);
    const bf16* Bc = g_Bc  + ((size_t)b*KK + ko0) * NN + s * (NN/FWD_S);
    const bf16* Bs = g_Bs  + ((size_t)b*KK + ko0) * NN + s * (NN/FWD_S);
    int arow = tid >> 3, ac8 = (tid & 7) * 8;
    for (int r0 = 0; r0 < NN/FWD_S; r0 += 64) {
        *(uint4*)&As[arow][ac8] = *(const uint4*)&A[(size_t)arow*NN + r0 + ac8];
        #pragma unroll
        for (int t = 0; t < 2; t++) {
            int brow = (tid >> 3) + t*32;
            *(uint4*)&Bsm[0][brow][ac8] = *(const uint4*)&Bc[(size_t)brow*NN + r0 + ac8];
            *(uint4*)&Bsm[1][brow][ac8] = *(const uint4*)&Bs[(size_t)brow*NN + r0 + ac8];
        }
        __syncthreads();
        #pragma unroll
        for (int kk = 0; kk < 64; kk += 16) {
            uint32_t af[4];
            int m = wm * 16;
            af[0] = *(const uint32_t*)&As[m+g  ][kk + 2*tig    ];
            af[1] = *(const uint32_t*)&As[m+g+8][kk + 2*tig    ];
            af[2] = *(const uint32_t*)&As[m+g  ][kk + 2*tig + 8];
            af[3] = *(const uint32_t*)&As[m+g+8][kk + 2*tig + 8];
            #pragma unroll
            for (int p = 0; p < 2; p++) {
                #pragma unroll
                for (int ns = 0; ns < 2; ns++) {
                    int n = wn * 16 + ns * 8;
                    uint32_t bf[2];
                    bf[0] = *(const uint32_t*)&Bsm[p][n+g][kk + 2*tig    ];
                    bf[1] = *(const uint32_t*)&Bsm[p][n+g][kk + 2*tig + 8];
                    mma_bf16(acc[p][ns], af, bf);
                }
            }
        }
        __syncthreads();
    }
    #pragma unroll
    for (int ns = 0; ns < 2; ns++) {
        int m = m0 + wm*16 + g;
        int k = ko0 + wn*16 + ns*8 + tig*2;
        size_t o0 = ((size_t)b*CC + m)*KK + k;
        size_t o1 = ((size_t)b*CC + m + 8)*KK + k;
        g_pc[s][o0]   = acc[0][ns][0];
        g_pc[s][o0+1] = acc[0][ns][1];
        g_pc[s][o1]   = acc[0][ns][2];
        g_pc[s][o1+1] = acc[0][ns][3];
        g_ps[s][o0]   = acc[1][ns][0];
        g_ps[s][o0+1] = acc[1][ns][1];
        g_ps[s][o1]   = acc[1][ns][2];
        g_ps[s][o1+1] = acc[1][ns][3];
    }
}

// -------- K3b: combine fwd partials -> packed bf16 [i][k][b] --------
__global__ void k_comb() {
    int idx = blockIdx.x * 256 + threadIdx.x;   // i*KK + k
    int i = idx >> 9;
    int k = idx & (KK - 1);
    bf16 outc[BB], outs[BB];
    #pragma unroll
    for (int b = 0; b < BB; b++) {
        size_t o = ((size_t)b*CC + i)*KK + k;
        outc[b] = __float2bfloat16(g_pc[0][o] + g_pc[1][o]);
        outs[b] = __float2bfloat16(g_ps[0][o] + g_ps[1][o]);
    }
    *(uint64_t*)&g_xck[(size_t)idx*BB] = *(uint64_t*)outc;
    *(uint64_t*)&g_xsk[(size_t)idx*BB] = *(uint64_t*)outs;
}

// -------- K4: mode mix, o-blocked (kills L2 coefficient re-reads) --------
// grid (CC/8, LL, KK/128); block 256 = 32 k-thr x 8 o-thr.
// Each thread: 1 o, 4 k, 4 b in registers. Weights streamed once from DRAM.
__global__ void k_mix_all(const float* __restrict__ wc, const float* __restrict__ ws) {
    int o = blockIdx.x * 8 + (threadIdx.x >> 5);
    int l = blockIdx.y;
    int k = blockIdx.z * 128 + (threadIdx.x & 31) * 4;
    const float inv_nf = 1.0f / (float)NFF;
    float accc[4][4] = {};   // [k][b]
    float accs[4][4] = {};
    const float* wc0 = wc + (((size_t)l*CC)*CC + o)*KK + k;
    const float* ws0 = ws + (((size_t)l*CC)*CC + o)*KK + k;
    #pragma unroll 2
    for (int i = 0; i < CC; i++) {
        float4 wcv = *(const float4*)(wc0 + (size_t)i*CC*KK);
        float4 wsv = *(const float4*)(ws0 + (size_t)i*CC*KK);
        float wcs[4] = {wcv.x, wcv.y, wcv.z, wcv.w};
        float wss[4] = {wsv.x, wsv.y, wsv.z, wsv.w};
        uint32_t xcw[8], xsw[8];
        *(uint4*)&xcw[0] = *(const uint4*)&g_xck[((size_t)i*KK + k)*BB];
        *(uint4*)&xcw[4] = *(const uint4*)&g_xck[((size_t)i*KK + k + 2)*BB];
        *(uint4*)&xsw[0] = *(const uint4*)&g_xsk[((size_t)i*KK + k)*BB];
        *(uint4*)&xsw[4] = *(const uint4*)&g_xsk[((size_t)i*KK + k + 2)*BB];
        #pragma unroll
        for (int kk = 0; kk < 4; kk++) {
            float2 c01 = __bfloat1622float2(*(const bf162*)&xcw[kk*2]);
            float2 c23 = __bfloat1622float2(*(const bf162*)&xcw[kk*2+1]);
            float2 s01 = __bfloat1622float2(*(const bf162*)&xsw[kk*2]);
            float2 s23 = __bfloat1622float2(*(const bf162*)&xsw[kk*2+1]);
            float xc[4] = {c01.x, c01.y, c23.x, c23.y};
            float xs[4] = {s01.x, s01.y, s23.x, s23.y};
            #pragma unroll
            for (int b = 0; b < BB; b++) {
                accc[kk][b] += xc[b]*wcs[kk] + xs[b]*wss[kk];
                accs[kk][b] += xc[b]*wss[kk] - xs[b]*wcs[kk];
            }
        }
    }
    #pragma unroll
    for (int b = 0; b < BB; b++) {
        size_t o4 = ((size_t)b*CC + o)*KK + k;
        bf162 fa01 = __floats2bfloat162_rn( 2.0f*inv_nf*accc[0][b],  2.0f*inv_nf*accc[1][b]);
        bf162 fa23 = __floats2bfloat162_rn( 2.0f*inv_nf*accc[2][b],  2.0f*inv_nf*accc[3][b]);
        bf162 fb01 = __floats2bfloat162_rn(-2.0f*inv_nf*accs[0][b], -2.0f*inv_nf*accs[1][b]);
        bf162 fb23 = __floats2bfloat162_rn(-2.0f*inv_nf*accs[2][b], -2.0f*inv_nf*accs[3][b]);
        uint32_t fa[2] = {*(uint32_t*)&fa01, *(uint32_t*)&fa23};
        uint32_t fb[2] = {*(uint32_t*)&fb01, *(uint32_t*)&fb23};
        *(uint64_t*)&g_fAb[l][o4] = *(uint64_t*)fa;
        *(uint64_t*)&g_fBb[l][o4] = *(uint64_t*)fb;
    }
}

// -------- K4b: f0h --------
__global__ void k_f0h_all(const float* __restrict__ w0, const float* __restrict__ convb) {
    int l = blockIdx.x;
    int t = threadIdx.x;
    int b = t >> 7, o = t & 127;
    float acc = 0.f;
    #pragma unroll 4
    for (int i = 0; i < CC; i++)
        acc += g_x0h[b*CC + i] * __ldg(&w0[((size_t)l*CC + i)*CC + o]);
    g_f0h[l][t] = acc * (1.0f / (float)NFF) + convb[l*CC + o];
}

// -------- K5a: inverse spectral GEMM --------
__global__ void k_inv_spec_all() {
    __shared__ bf16 As[2][64][40];
    __shared__ bf16 Bsm[2][128][40];
    int z  = blockIdx.z;
    int b  = z & (BB-1);
    int l  = z >> 2;
    int m0 = blockIdx.y * 64;
    int n0 = blockIdx.x * 128;
    int tid = threadIdx.x;
    int lane = tid & 31, wid = tid >> 5;
    int wm = wid >> 2, wn = wid & 3;
    int g = lane >> 2, tig = lane & 3;
    float acc[2][4][4] = {};
    const bf16* fA = g_fAb[l] + ((size_t)b*CC + m0)*KK;
    const bf16* fB = g_fBb[l] + ((size_t)b*CC + m0)*KK;
    const bf16* BcT = g_BcT + ((size_t)b*NN + n0)*KK;
    const bf16* BsT = g_BsT + ((size_t)b*NN + n0)*KK;
    int arow = tid >> 2, ac8 = (tid & 3) * 8;
    for (int r0 = 0; r0 < KK; r0 += 32) {
        *(uint4*)&As[0][arow][ac8] = *(const uint4*)&fA[(size_t)arow*KK + r0 + ac8];
        *(uint4*)&As[1][arow][ac8] = *(const uint4*)&fB[(size_t)arow*KK + r0 + ac8];
        #pragma unroll
        for (int t = 0; t < 2; t++) {
            int brow = (tid >> 2) + t*64;
            *(uint4*)&Bsm[0][brow][ac8] = *(const uint4*)&BcT[(size_t)brow*KK + r0 + ac8];
            *(uint4*)&Bsm[1][brow][ac8] = *(const uint4*)&BsT[(size_t)brow*KK + r0 + ac8];
        }
        __syncthreads();
        #pragma unroll
        for (int kk = 0; kk < 32; kk += 16) {
            #pragma unroll
            for (int p = 0; p < 2; p++) {
                uint32_t af[2][4];
                #pragma unroll
                for (int ms = 0; ms < 2; ms++) {
                    int m = wm*32 + ms*16;
                    af[ms][0] = *(const uint32_t*)&As[p][m+g  ][kk + 2*tig    ];
                    af[ms][1] = *(const uint32_t*)&As[p][m+g+8][kk + 2*tig    ];
                    af[ms][2] = *(const uint32_t*)&As[p][m+g  ][kk + 2*tig + 8];
                    af[ms][3] = *(const uint32_t*)&As[p][m+g+8][kk + 2*tig + 8];
                }
                #pragma unroll
                for (int ns = 0; ns < 4; ns++) {
                    int n = wn*32 + ns*8;
                    uint32_t bf[2];
                    bf[0] = *(const uint32_t*)&Bsm[p][n+g][kk + 2*tig    ];
                    bf[1] = *(const uint32_t*)&Bsm[p][n+g][kk + 2*tig + 8];
                    #pragma unroll
                    for (int ms = 0; ms < 2; ms++)
                        mma_bf16(acc[ms][ns], af[ms], bf);
                }
            }
        }
        __syncthreads();
    }
    bf16* X1 = g_x1b[l] + (size_t)b*CC*NN;
    #pragma unroll
    for (int ms = 0; ms < 2; ms++) {
        #pragma unroll
        for (int ns = 0; ns < 4; ns++) {
            int m = m0 + wm*32 + ms*16 + g;
            int n = n0 + wn*32 + ns*8 + tig*2;
            *reinterpret_cast<bf162*>(&X1[(size_t)m*NN + n]) =
                __floats2bfloat162_rn(acc[ms][ns][0], acc[ms][ns][1]);
            *reinterpret_cast<bf162*>(&X1[(size_t)(m+8)*NN + n]) =
                __floats2bfloat162_rn(acc[ms][ns][2], acc[ms][ns][3]);
        }
    }
}

// -------- K5b: conv via 3xTF32 + epilogue --------
__global__ void k_conv_tc(const float* __restrict__ convw, int l, int cur) {
    __shared__ float Ah[64][20], Al[64][20];
    __shared__ float Bh[16][132], Bl[16][132];
    int b  = blockIdx.z;
    int m0 = blockIdx.y * 64;
    int n0 = blockIdx.x * 128;
    int tid = threadIdx.x;
    int lane = tid & 31, wid = tid >> 5;
    int wm = wid >> 2, wn = wid & 3;
    int g = lane >> 2, tig = lane & 3;
    float acc[2][4][4] = {};
    const float* W = convw + (size_t)l*CC*CC + (size_t)m0*CC;
    const float* H = g_h[cur] + (size_t)b*CC*NN;
    int arow = tid >> 2, ac4 = (tid & 3) * 4;
    for (int r0 = 0; r0 < CC; r0 += 16) {
        float4 va = *(const float4*)&W[(size_t)arow*CC + r0 + ac4];
        float h0,l0,h1,l1,h2,l2,h3,l3;
        split_tf32(va.x, h0, l0); split_tf32(va.y, h1, l1);
        split_tf32(va.z, h2, l2); split_tf32(va.w, h3, l3);
        Ah[arow][ac4] = h0; Ah[arow][ac4+1] = h1; Ah[arow][ac4+2] = h2; Ah[arow][ac4+3] = h3;
        Al[arow][ac4] = l0; Al[arow][ac4+1] = l1; Al[arow][ac4+2] = l2; Al[arow][ac4+3] = l3;
        #pragma unroll
        for (int t = 0; t < 2; t++) {
            int idx = tid + t*256;
            int brow = idx >> 5, bc4 = (idx & 31) * 4;
            float4 vb = *(const float4*)&H[(size_t)(r0+brow)*NN + n0 + bc4];
            float bh0,bl0,bh1,bl1,bh2,bl2,bh3,bl3;
            split_tf32(vb.x, bh0, bl0); split_tf32(vb.y, bh1, bl1);
            split_tf32(vb.z, bh2, bl2); split_tf32(vb.w, bh3, bl3);
            Bh[brow][bc4] = bh0; Bh[brow][bc4+1] = bh1; Bh[brow][bc4+2] = bh2; Bh[brow][bc4+3] = bh3;
            Bl[brow][bc4] = bl0; Bl[brow][bc4+1] = bl1; Bl[brow][bc4+2] = bl2; Bl[brow][bc4+3] = bl3;
        }
        __syncthreads();
        #pragma unroll
        for (int kk = 0; kk < 16; kk += 8) {
            uint32_t afh[2][4], afl[2][4];
            #pragma unroll
            for (int ms = 0; ms < 2; ms++) {
                int m = wm*32 + ms*16;
                afh[ms][0] = __float_as_uint(Ah[m+g  ][kk+tig  ]);
                afh[ms][1] = __float_as_uint(Ah[m+g+8][kk+tig  ]);
                afh[ms][2] = __float_as_uint(Ah[m+g  ][kk+tig+4]);
                afh[ms][3] = __float_as_uint(Ah[m+g+8][kk+tig+4]);
                afl[ms][0] = __float_as_uint(Al[m+g  ][kk+tig  ]);
                afl[ms][1] = __float_as_uint(Al[m+g+8][kk+tig  ]);
                afl[ms][2] = __float_as_uint(Al[m+g  ][kk+tig+4]);
                afl[ms][3] = __float_as_uint(Al[m+g+8][kk+tig+4]);
            }
            #pragma unroll
            for (int ns = 0; ns < 4; ns++) {
                int n = wn*32 + ns*8;
                uint32_t bfh[2], bfl[2];
                bfh[0] = __float_as_uint(Bh[kk+tig  ][n+g]);
                bfh[1] = __float_as_uint(Bh[kk+tig+4][n+g]);
                bfl[0] = __float_as_uint(Bl[kk+tig  ][n+g]);
                bfl[1] = __float_as_uint(Bl[kk+tig+4][n+g]);
                #pragma unroll
                for (int ms = 0; ms < 2; ms++) {
                    mma_tf32(acc[ms][ns], afh[ms], bfh);
                    mma_tf32(acc[ms][ns], afh[ms], bfl);
                    mma_tf32(acc[ms][ns], afl[ms], bfh);
                }
            }
        }
        __syncthreads();
    }
    int nxt = cur ^ 1;
    const bf16* X1 = g_x1b[l] + (size_t)b*CC*NN;
    float* Hn = g_h[nxt] + (size_t)b*CC*NN;
    #pragma unroll
    for (int ms = 0; ms < 2; ms++) {
        #pragma unroll
        for (int ns = 0; ns < 4; ns++) {
            int m = m0 + wm*32 + ms*16 + g;
            int n = n0 + wn*32 + ns*8 + tig*2;
            float bias0 = g_f0h[l][b*CC + m];
            float bias1 = g_f0h[l][b*CC + m + 8];
            float2 x1a = __bfloat1622float2(*reinterpret_cast<const bf162*>(&X1[(size_t)m*NN + n]));
            float2 x1b = __bfloat1622float2(*reinterpret_cast<const bf162*>(&X1[(size_t)(m+8)*NN + n]));
            float v0 = acc[ms][ns][0] + bias0 + x1a.x;
            float v1 = acc[ms][ns][1] + bias0 + x1a.y;
            float v2 = acc[ms][ns][2] + bias1 + x1b.x;
            float v3 = acc[ms][ns][3] + bias1 + x1b.y;
            if (l < LL - 1) {
                v0 = gelu_exact(v0); v1 = gelu_exact(v1);
                v2 = gelu_exact(v2); v3 = gelu_exact(v3);
            }
            Hn[(size_t)m*NN + n]         = v0;
            Hn[(size_t)m*NN + n + 1]     = v1;
            Hn[(size_t)(m+8)*NN + n]     = v2;
            Hn[(size_t)(m+8)*NN + n + 1] = v3;
        }
    }
}

// -------- K6: head --------
__global__ void k_head(const float* __restrict__ w1, const float* __restrict__ b1,
                       const float* __restrict__ w2, const float* __restrict__ b2,
                       float* __restrict__ out, int cur) {
    __shared__ float sh[CC][32];
    __shared__ float red[CC][33];
    int b  = blockIdx.y;
    int n0 = blockIdx.x * 32;
    int f = threadIdx.x;
    const float* H = g_h[cur] + (size_t)b*CC*NN + n0;
    #pragma unroll 4
    for (int c4 = 0; c4 < CC; c4 += 4) {
        int row = c4 + (f >> 5);
        int col = f & 31;
        sh[row][col] = H[(size_t)row*NN + col];
    }
    __syncthreads();
    float acc[32];
    float bv = b1[f];
    #pragma unroll
    for (int j = 0; j < 32; j++) acc[j] = bv;
    for (int c = 0; c < CC; c++) {
        float w = __ldg(&w1[(size_t)c*FCD + f]);
        #pragma unroll
        for (int j = 0; j < 32; j++) acc[j] += sh[c][j] * w;
    }
    float w2f = __ldg(&w2[f]);
    #pragma unroll
    for (int j = 0; j < 32; j++)
        red[f][j] = gelu_exact(acc[j]) * w2f;
    __syncthreads();
    if (f < 32) {
        float s = b2[0];
        #pragma unroll 8
        for (int q = 0; q < CC; q++) s += red[q][f];
        out[(size_t)b*NN + n0 + f] = s;
    }
}

// -------- launch --------
extern "C" void kernel_launch(void* const* d_in, const int* in_sizes, int n_in,
                              void* d_out, int out_size) {
    (void)in_sizes; (void)n_in; (void)out_size;
    const float* x     = (const float*)d_in[0];
    const float* xf    = (const float*)d_in[1];
    const int*   ind   = (const int*)  d_in[2];
    const float* modes = (const float*)d_in[3];
    const float* fc0_w = (const float*)d_in[4];
    const float* fc0_b = (const float*)d_in[5];
    const float* wc    = (const float*)d_in[6];
    const float* ws    = (const float*)d_in[7];
    const float* w0    = (const float*)d_in[8];
    const float* convw = (const float*)d_in[9];
    const float* convb = (const float*)d_in[10];
    const float* fc1_w = (const float*)d_in[11];
    const float* fc1_b = (const float*)d_in[12];
    const float* fc2_w = (const float*)d_in[13];
    const float* fc2_b = (const float*)d_in[14];
    float* out = (float*)d_out;

    dim3 g1(NN/32, BB);
    k_basis<<<g1, 256>>>(xf, ind, modes);
    dim3 g2(NN/256, CC, BB);
    k_fc0<<<g2, 256>>>(x, fc0_w, fc0_b);
    dim3 g3(KK/64, CC/32, BB*FWD_S);
    k_fwd_tc<<<g3, 256>>>();
    k_comb<<<CC*KK/256, 256>>>();

    // mode mix: o-blocked, weights streamed once
    dim3 g4(CC/8, LL, KK/128);
    k_mix_all<<<g4, 256>>>(wc, ws);

    k_x0h<<<BB*CC, 256>>>();
    k_f0h_all<<<LL, BB*CC>>>(w0, convb);
    dim3 g5(NN/128, CC/64, BB*LL);
    k_inv_spec_all<<<g5, 256>>>();

    int cur = 0;
    for (int l = 0; l < LL; l++) {
        dim3 g6(NN/128, CC/64, BB);
        k_conv_tc<<<g6, 256>>>(convw, l, cur);
        cur ^= 1;
    }

    dim3 g7(NN/32, BB);
    k_head<<<g7, 128>>>(fc1_w, fc1_b, fc2_w, fc2_b, out, cur);
}

// round 13
// speedup vs baseline: 1.2213x; 1.0106x over previous
#include <cuda_runtime.h>
#include <cuda_bf16.h>
#include <math.h>
#include <stdint.h>

#define BB 4
#define NN 4096
#define NFF 8192
#define KK 512
#define CC 128
#define LL 4
#define INDIM 3
#define FCD 128
#define FWD_S 2

typedef __nv_bfloat16 bf16;
typedef __nv_bfloat162 bf162;

// -------- scratch --------
__device__ bf16  g_Bc [BB*KK*NN];      // basis [b][k][n]
__device__ bf16  g_Bs [BB*KK*NN];
__device__ bf16  g_BcT[BB*NN*KK];      // basis [b][n][k]
__device__ bf16  g_BsT[BB*NN*KK];
__device__ float g_wqn[BB*NN];
__device__ float g_h[2][BB*CC*NN];
__device__ bf16  g_hwb[BB*CC*NN];      // h0*wqn bf16
__device__ float g_pc[FWD_S][BB*CC*KK];  // forward partials
__device__ float g_ps[FWD_S][BB*CC*KK];
__device__ bf16  g_xck[CC*KK*BB];      // combined fwd coeffs, packed [i][k][b]
__device__ bf16  g_xsk[CC*KK*BB];
__device__ bf16  g_fAb[LL][BB*CC*KK];
__device__ bf16  g_fBb[LL][BB*CC*KK];
__device__ bf16  g_x1b[LL][BB*CC*NN];  // spectral inverse, bf16
__device__ float g_x0h[BB*CC];
__device__ float g_f0h[LL][BB*CC];

__device__ __forceinline__ float gelu_exact(float v) {
    return 0.5f * v * (1.0f + erff(v * 0.7071067811865476f));
}
__device__ __forceinline__ void split_bf16(float v, bf16& hi, bf16& lo) {
    hi = __float2bfloat16(v);
    lo = __float2bfloat16(v - __bfloat162float(hi));
}
__device__ __forceinline__ void mma_bf16(float (&d)[4], const uint32_t (&a)[4],
                                         const uint32_t (&b)[2]) {
    asm volatile(
        "mma.sync.aligned.m16n8k16.row.col.f32.bf16.bf16.f32 "
        "{%0,%1,%2,%3}, {%4,%5,%6,%7}, {%8,%9}, {%0,%1,%2,%3};"
        : "+f"(d[0]), "+f"(d[1]), "+f"(d[2]), "+f"(d[3])
        : "r"(a[0]), "r"(a[1]), "r"(a[2]), "r"(a[3]), "r"(b[0]), "r"(b[1]));
}

// -------- K1: basis via integer-mode angle addition + fused wqn --------
__global__ void k_basis(const float* __restrict__ xf, const int* __restrict__ ind,
                        const float* __restrict__ modes) {
    __shared__ float txC[33][32], txS[33][32], tyC[33][32], tyS[33][32];
    __shared__ bf16 tc[32][34], ts[32][34];
    int b  = blockIdx.y;
    int n0 = blockIdx.x * 32;
    int tid = threadIdx.x;
    int tx = tid & 31;
    int ty = tid >> 5;
    if (ty == 0) {
        int n = n0 + tx;
        int f = __ldg(&ind[n]);
        const float* xfp = xf + ((size_t)b*NFF + f)*4;
        float gx = __ldg(&xfp[0]);
        float gy = __ldg(&xfp[1]);
        g_wqn[b*NN + n] = __ldg(&xfp[2]) * (float)NN;
        float c1, s1;
        sincosf(gx, &s1, &c1);
        txC[16][tx] = 1.f; txS[16][tx] = 0.f;
        float cj = c1, sj = s1;
        #pragma unroll
        for (int j = 1; j <= 16; j++) {
            txC[16+j][tx] = cj;  txS[16+j][tx] = sj;
            txC[16-j][tx] = cj;  txS[16-j][tx] = -sj;
            float cn = cj*c1 - sj*s1;
            float sn = sj*c1 + cj*s1;
            cj = cn; sj = sn;
        }
        sincosf(gy, &s1, &c1);
        tyC[16][tx] = 1.f; tyS[16][tx] = 0.f;
        cj = c1; sj = s1;
        #pragma unroll
        for (int j = 1; j <= 16; j++) {
            tyC[16+j][tx] = cj;  tyS[16+j][tx] = sj;
            tyC[16-j][tx] = cj;  tyS[16-j][tx] = -sj;
            float cn = cj*c1 - sj*s1;
            float sn = sj*c1 + cj*s1;
            cj = cn; sj = sn;
        }
    }
    __syncthreads();
    for (int k0 = 0; k0 < KK; k0 += 32) {
        #pragma unroll
        for (int jj = 0; jj < 4; jj++) {
            int kr = ty*4 + jj;
            int k = k0 + kr;
            int jx = (int)__ldg(&modes[2*k])   + 16;
            int jy = (int)__ldg(&modes[2*k+1]) + 16;
            float ca = txC[jx][tx], sa = txS[jx][tx];
            float cb = tyC[jy][tx], sb = tyS[jy][tx];
            float c = ca*cb - sa*sb;
            float s = sa*cb + ca*sb;
            bf16 cb16 = __float2bfloat16(c);
            bf16 sb16 = __float2bfloat16(s);
            tc[kr][tx] = cb16;
            ts[kr][tx] = sb16;
            g_Bc[((size_t)b*KK + k)*NN + n0 + tx] = cb16;
            g_Bs[((size_t)b*KK + k)*NN + n0 + tx] = sb16;
        }
        __syncthreads();
        #pragma unroll
        for (int jj = 0; jj < 4; jj++) {
            int nr = ty*4 + jj;
            int n = n0 + nr;
            g_BcT[((size_t)b*NN + n)*KK + k0 + tx] = tc[tx][nr];
            g_BsT[((size_t)b*NN + n)*KK + k0 + tx] = ts[tx][nr];
        }
        __syncthreads();
    }
}

// -------- K2: fc0 --------
__global__ void k_fc0(const float* __restrict__ x, const float* __restrict__ w,
                      const float* __restrict__ bias) {
    int n = blockIdx.x * blockDim.x + threadIdx.x;
    int c = blockIdx.y;
    int b = blockIdx.z;
    const float* xp = x + ((size_t)b * NN + n) * INDIM;
    float acc = bias[c]
              + xp[0] * w[0*CC + c]
              + xp[1] * w[1*CC + c]
              + xp[2] * w[2*CC + c];
    size_t o = ((size_t)b*CC + c) * NN + n;
    g_h[0][o] = acc;
    g_hwb[o]  = __float2bfloat16(acc * g_wqn[b*NN + n]);
}

// -------- K2b: x0h --------
__global__ void k_x0h() {
    int bc = blockIdx.x;
    const bf162* p = reinterpret_cast<const bf162*>(g_hwb + (size_t)bc * NN);
    float acc = 0.f;
    for (int n = threadIdx.x; n < NN/2; n += 256) {
        float2 v = __bfloat1622float2(p[n]);
        acc += v.x + v.y;
    }
    __shared__ float red[256];
    red[threadIdx.x] = acc;
    __syncthreads();
    for (int s = 128; s > 0; s >>= 1) {
        if (threadIdx.x < s) red[threadIdx.x] += red[threadIdx.x + s];
        __syncthreads();
    }
    if (threadIdx.x == 0) g_x0h[bc] = red[0];
}

// -------- K3: forward dual GEMM, bf16 TC, split-N --------
__global__ void k_fwd_tc() {
    __shared__ bf16 As[32][72];
    __shared__ bf16 Bsm[2][64][72];
    int z   = blockIdx.z;
    int b   = z >> 1;
    int s   = z & 1;
    int m0  = blockIdx.y * 32;
    int ko0 = blockIdx.x * 64;
    int tid = threadIdx.x;
    int lane = tid & 31, wid = tid >> 5;
    int wm = wid >> 2, wn = wid & 3;
    int g = lane >> 2, tig = lane & 3;
    float acc[2][2][4] = {};
    const bf16* A  = g_hwb + ((size_t)b*CC + m0) * NN + s * (NN/FWD_S);
    const bf16* Bc = g_Bc  + ((size_t)b*KK + ko0) * NN + s * (NN/FWD_S);
    const bf16* Bs = g_Bs  + ((size_t)b*KK + ko0) * NN + s * (NN/FWD_S);
    int arow = tid >> 3, ac8 = (tid & 7) * 8;
    for (int r0 = 0; r0 < NN/FWD_S; r0 += 64) {
        *(uint4*)&As[arow][ac8] = *(const uint4*)&A[(size_t)arow*NN + r0 + ac8];
        #pragma unroll
        for (int t = 0; t < 2; t++) {
            int brow = (tid >> 3) + t*32;
            *(uint4*)&Bsm[0][brow][ac8] = *(const uint4*)&Bc[(size_t)brow*NN + r0 + ac8];
            *(uint4*)&Bsm[1][brow][ac8] = *(const uint4*)&Bs[(size_t)brow*NN + r0 + ac8];
        }
        __syncthreads();
        #pragma unroll
        for (int kk = 0; kk < 64; kk += 16) {
            uint32_t af[4];
            int m = wm * 16;
            af[0] = *(const uint32_t*)&As[m+g  ][kk + 2*tig    ];
            af[1] = *(const uint32_t*)&As[m+g+8][kk + 2*tig    ];
            af[2] = *(const uint32_t*)&As[m+g  ][kk + 2*tig + 8];
            af[3] = *(const uint32_t*)&As[m+g+8][kk + 2*tig + 8];
            #pragma unroll
            for (int p = 0; p < 2; p++) {
                #pragma unroll
                for (int ns = 0; ns < 2; ns++) {
                    int n = wn * 16 + ns * 8;
                    uint32_t bf[2];
                    bf[0] = *(const uint32_t*)&Bsm[p][n+g][kk + 2*tig    ];
                    bf[1] = *(const uint32_t*)&Bsm[p][n+g][kk + 2*tig + 8];
                    mma_bf16(acc[p][ns], af, bf);
                }
            }
        }
        __syncthreads();
    }
    #pragma unroll
    for (int ns = 0; ns < 2; ns++) {
        int m = m0 + wm*16 + g;
        int k = ko0 + wn*16 + ns*8 + tig*2;
        size_t o0 = ((size_t)b*CC + m)*KK + k;
        size_t o1 = ((size_t)b*CC + m + 8)*KK + k;
        g_pc[s][o0]   = acc[0][ns][0];
        g_pc[s][o0+1] = acc[0][ns][1];
        g_pc[s][o1]   = acc[0][ns][2];
        g_pc[s][o1+1] = acc[0][ns][3];
        g_ps[s][o0]   = acc[1][ns][0];
        g_ps[s][o0+1] = acc[1][ns][1];
        g_ps[s][o1]   = acc[1][ns][2];
        g_ps[s][o1+1] = acc[1][ns][3];
    }
}

// -------- K3b: combine fwd partials -> packed bf16 [i][k][b] --------
__global__ void k_comb() {
    int idx = blockIdx.x * 256 + threadIdx.x;   // i*KK + k
    int i = idx >> 9;
    int k = idx & (KK - 1);
    bf16 outc[BB], outs[BB];
    #pragma unroll
    for (int b = 0; b < BB; b++) {
        size_t o = ((size_t)b*CC + i)*KK + k;
        outc[b] = __float2bfloat16(g_pc[0][o] + g_pc[1][o]);
        outs[b] = __float2bfloat16(g_ps[0][o] + g_ps[1][o]);
    }
    *(uint64_t*)&g_xck[(size_t)idx*BB] = *(uint64_t*)outc;
    *(uint64_t*)&g_xsk[(size_t)idx*BB] = *(uint64_t*)outs;
}

// -------- K4: mode mix, o-blocked --------
__global__ void k_mix_all(const float* __restrict__ wc, const float* __restrict__ ws) {
    int o = blockIdx.x * 8 + (threadIdx.x >> 5);
    int l = blockIdx.y;
    int k = blockIdx.z * 128 + (threadIdx.x & 31) * 4;
    const float inv_nf = 1.0f / (float)NFF;
    float accc[4][4] = {};
    float accs[4][4] = {};
    const float* wc0 = wc + (((size_t)l*CC)*CC + o)*KK + k;
    const float* ws0 = ws + (((size_t)l*CC)*CC + o)*KK + k;
    #pragma unroll 2
    for (int i = 0; i < CC; i++) {
        float4 wcv = *(const float4*)(wc0 + (size_t)i*CC*KK);
        float4 wsv = *(const float4*)(ws0 + (size_t)i*CC*KK);
        float wcs[4] = {wcv.x, wcv.y, wcv.z, wcv.w};
        float wss[4] = {wsv.x, wsv.y, wsv.z, wsv.w};
        uint32_t xcw[8], xsw[8];
        *(uint4*)&xcw[0] = *(const uint4*)&g_xck[((size_t)i*KK + k)*BB];
        *(uint4*)&xcw[4] = *(const uint4*)&g_xck[((size_t)i*KK + k + 2)*BB];
        *(uint4*)&xsw[0] = *(const uint4*)&g_xsk[((size_t)i*KK + k)*BB];
        *(uint4*)&xsw[4] = *(const uint4*)&g_xsk[((size_t)i*KK + k + 2)*BB];
        #pragma unroll
        for (int kk = 0; kk < 4; kk++) {
            float2 c01 = __bfloat1622float2(*(const bf162*)&xcw[kk*2]);
            float2 c23 = __bfloat1622float2(*(const bf162*)&xcw[kk*2+1]);
            float2 s01 = __bfloat1622float2(*(const bf162*)&xsw[kk*2]);
            float2 s23 = __bfloat1622float2(*(const bf162*)&xsw[kk*2+1]);
            float xc[4] = {c01.x, c01.y, c23.x, c23.y};
            float xs[4] = {s01.x, s01.y, s23.x, s23.y};
            #pragma unroll
            for (int b = 0; b < BB; b++) {
                accc[kk][b] += xc[b]*wcs[kk] + xs[b]*wss[kk];
                accs[kk][b] += xc[b]*wss[kk] - xs[b]*wcs[kk];
            }
        }
    }
    #pragma unroll
    for (int b = 0; b < BB; b++) {
        size_t o4 = ((size_t)b*CC + o)*KK + k;
        bf162 fa01 = __floats2bfloat162_rn( 2.0f*inv_nf*accc[0][b],  2.0f*inv_nf*accc[1][b]);
        bf162 fa23 = __floats2bfloat162_rn( 2.0f*inv_nf*accc[2][b],  2.0f*inv_nf*accc[3][b]);
        bf162 fb01 = __floats2bfloat162_rn(-2.0f*inv_nf*accs[0][b], -2.0f*inv_nf*accs[1][b]);
        bf162 fb23 = __floats2bfloat162_rn(-2.0f*inv_nf*accs[2][b], -2.0f*inv_nf*accs[3][b]);
        uint32_t fa[2] = {*(uint32_t*)&fa01, *(uint32_t*)&fa23};
        uint32_t fb[2] = {*(uint32_t*)&fb01, *(uint32_t*)&fb23};
        *(uint64_t*)&g_fAb[l][o4] = *(uint64_t*)fa;
        *(uint64_t*)&g_fBb[l][o4] = *(uint64_t*)fb;
    }
}

// -------- K4b: f0h --------
__global__ void k_f0h_all(const float* __restrict__ w0, const float* __restrict__ convb) {
    int l = blockIdx.x;
    int t = threadIdx.x;
    int b = t >> 7, o = t & 127;
    float acc = 0.f;
    #pragma unroll 4
    for (int i = 0; i < CC; i++)
        acc += g_x0h[b*CC + i] * __ldg(&w0[((size_t)l*CC + i)*CC + o]);
    g_f0h[l][t] = acc * (1.0f / (float)NFF) + convb[l*CC + o];
}

// -------- K5a: inverse spectral GEMM (b slow in z for L2 basis reuse) --------
__global__ void k_inv_spec_all() {
    __shared__ bf16 As[2][64][40];
    __shared__ bf16 Bsm[2][128][40];
    int z  = blockIdx.z;
    int l  = z & (LL-1);   // layers contiguous: same-b CTAs run together -> BcT hits L2
    int b  = z >> 2;
    int m0 = blockIdx.y * 64;
    int n0 = blockIdx.x * 128;
    int tid = threadIdx.x;
    int lane = tid & 31, wid = tid >> 5;
    int wm = wid >> 2, wn = wid & 3;
    int g = lane >> 2, tig = lane & 3;
    float acc[2][4][4] = {};
    const bf16* fA = g_fAb[l] + ((size_t)b*CC + m0)*KK;
    const bf16* fB = g_fBb[l] + ((size_t)b*CC + m0)*KK;
    const bf16* BcT = g_BcT + ((size_t)b*NN + n0)*KK;
    const bf16* BsT = g_BsT + ((size_t)b*NN + n0)*KK;
    int arow = tid >> 2, ac8 = (tid & 3) * 8;
    for (int r0 = 0; r0 < KK; r0 += 32) {
        *(uint4*)&As[0][arow][ac8] = *(const uint4*)&fA[(size_t)arow*KK + r0 + ac8];
        *(uint4*)&As[1][arow][ac8] = *(const uint4*)&fB[(size_t)arow*KK + r0 + ac8];
        #pragma unroll
        for (int t = 0; t < 2; t++) {
            int brow = (tid >> 2) + t*64;
            *(uint4*)&Bsm[0][brow][ac8] = *(const uint4*)&BcT[(size_t)brow*KK + r0 + ac8];
            *(uint4*)&Bsm[1][brow][ac8] = *(const uint4*)&BsT[(size_t)brow*KK + r0 + ac8];
        }
        __syncthreads();
        #pragma unroll
        for (int kk = 0; kk < 32; kk += 16) {
            #pragma unroll
            for (int p = 0; p < 2; p++) {
                uint32_t af[2][4];
                #pragma unroll
                for (int ms = 0; ms < 2; ms++) {
                    int m = wm*32 + ms*16;
                    af[ms][0] = *(const uint32_t*)&As[p][m+g  ][kk + 2*tig    ];
                    af[ms][1] = *(const uint32_t*)&As[p][m+g+8][kk + 2*tig    ];
                    af[ms][2] = *(const uint32_t*)&As[p][m+g  ][kk + 2*tig + 8];
                    af[ms][3] = *(const uint32_t*)&As[p][m+g+8][kk + 2*tig + 8];
                }
                #pragma unroll
                for (int ns = 0; ns < 4; ns++) {
                    int n = wn*32 + ns*8;
                    uint32_t bf[2];
                    bf[0] = *(const uint32_t*)&Bsm[p][n+g][kk + 2*tig    ];
                    bf[1] = *(const uint32_t*)&Bsm[p][n+g][kk + 2*tig + 8];
                    #pragma unroll
                    for (int ms = 0; ms < 2; ms++)
                        mma_bf16(acc[ms][ns], af[ms], bf);
                }
            }
        }
        __syncthreads();
    }
    bf16* X1 = g_x1b[l] + (size_t)b*CC*NN;
    #pragma unroll
    for (int ms = 0; ms < 2; ms++) {
        #pragma unroll
        for (int ns = 0; ns < 4; ns++) {
            int m = m0 + wm*32 + ms*16 + g;
            int n = n0 + wn*32 + ns*8 + tig*2;
            *reinterpret_cast<bf162*>(&X1[(size_t)m*NN + n]) =
                __floats2bfloat162_rn(acc[ms][ns][0], acc[ms][ns][1]);
            *reinterpret_cast<bf162*>(&X1[(size_t)(m+8)*NN + n]) =
                __floats2bfloat162_rn(acc[ms][ns][2], acc[ms][ns][3]);
        }
    }
}

// -------- K5b: conv via bf16 hi/lo split (3 bf16 mma per k16) + epilogue --------
__global__ void k_conv_tc(const float* __restrict__ convw, int l, int cur) {
    __shared__ bf16 Ah[64][20], Al[64][20];
    __shared__ bf16 Bh[128][18], Bl[128][18];
    int b  = blockIdx.z;
    int m0 = blockIdx.y * 64;
    int n0 = blockIdx.x * 128;
    int tid = threadIdx.x;
    int lane = tid & 31, wid = tid >> 5;
    int wm = wid >> 2, wn = wid & 3;
    int g = lane >> 2, tig = lane & 3;
    float acc[2][4][4] = {};
    const float* W = convw + (size_t)l*CC*CC + (size_t)m0*CC;
    const float* H = g_h[cur] + (size_t)b*CC*NN;
    int arow = tid >> 2, ac4 = (tid & 3) * 4;
    for (int r0 = 0; r0 < CC; r0 += 16) {
        // A (weights 64m x 16k) split hi/lo
        float4 va = *(const float4*)&W[(size_t)arow*CC + r0 + ac4];
        bf16 h0,l0,h1,l1,h2,l2,h3,l3;
        split_bf16(va.x, h0, l0); split_bf16(va.y, h1, l1);
        split_bf16(va.z, h2, l2); split_bf16(va.w, h3, l3);
        Ah[arow][ac4] = h0; Ah[arow][ac4+1] = h1; Ah[arow][ac4+2] = h2; Ah[arow][ac4+3] = h3;
        Al[arow][ac4] = l0; Al[arow][ac4+1] = l1; Al[arow][ac4+2] = l2; Al[arow][ac4+3] = l3;
        // B (h: 16k x 128n) split hi/lo, stored [n][k]
        #pragma unroll
        for (int t = 0; t < 2; t++) {
            int idx = tid + t*256;
            int brow = idx >> 5, bc4 = (idx & 31) * 4;
            float4 vb = *(const float4*)&H[(size_t)(r0+brow)*NN + n0 + bc4];
            bf16 bh, bl;
            split_bf16(vb.x, bh, bl); Bh[bc4  ][brow] = bh; Bl[bc4  ][brow] = bl;
            split_bf16(vb.y, bh, bl); Bh[bc4+1][brow] = bh; Bl[bc4+1][brow] = bl;
            split_bf16(vb.z, bh, bl); Bh[bc4+2][brow] = bh; Bl[bc4+2][brow] = bl;
            split_bf16(vb.w, bh, bl); Bh[bc4+3][brow] = bh; Bl[bc4+3][brow] = bl;
        }
        __syncthreads();
        // one k16 mma step per r0 chunk
        uint32_t afh[2][4], afl[2][4];
        #pragma unroll
        for (int ms = 0; ms < 2; ms++) {
            int m = wm*32 + ms*16;
            afh[ms][0] = *(const uint32_t*)&Ah[m+g  ][2*tig    ];
            afh[ms][1] = *(const uint32_t*)&Ah[m+g+8][2*tig    ];
            afh[ms][2] = *(const uint32_t*)&Ah[m+g  ][2*tig + 8];
            afh[ms][3] = *(const uint32_t*)&Ah[m+g+8][2*tig + 8];
            afl[ms][0] = *(const uint32_t*)&Al[m+g  ][2*tig    ];
            afl[ms][1] = *(const uint32_t*)&Al[m+g+8][2*tig    ];
            afl[ms][2] = *(const uint32_t*)&Al[m+g  ][2*tig + 8];
            afl[ms][3] = *(const uint32_t*)&Al[m+g+8][2*tig + 8];
        }
        #pragma unroll
        for (int ns = 0; ns < 4; ns++) {
            int n = wn*32 + ns*8;
            uint32_t bfh[2], bfl[2];
            bfh[0] = *(const uint32_t*)&Bh[n+g][2*tig    ];
            bfh[1] = *(const uint32_t*)&Bh[n+g][2*tig + 8];
            bfl[0] = *(const uint32_t*)&Bl[n+g][2*tig    ];
            bfl[1] = *(const uint32_t*)&Bl[n+g][2*tig + 8];
            #pragma unroll
            for (int ms = 0; ms < 2; ms++) {
                mma_bf16(acc[ms][ns], afh[ms], bfh);
                mma_bf16(acc[ms][ns], afh[ms], bfl);
                mma_bf16(acc[ms][ns], afl[ms], bfh);
            }
        }
        __syncthreads();
    }
    int nxt = cur ^ 1;
    const bf16* X1 = g_x1b[l] + (size_t)b*CC*NN;
    float* Hn = g_h[nxt] + (size_t)b*CC*NN;
    #pragma unroll
    for (int ms = 0; ms < 2; ms++) {
        #pragma unroll
        for (int ns = 0; ns < 4; ns++) {
            int m = m0 + wm*32 + ms*16 + g;
            int n = n0 + wn*32 + ns*8 + tig*2;
            float bias0 = g_f0h[l][b*CC + m];
            float bias1 = g_f0h[l][b*CC + m + 8];
            float2 x1a = __bfloat1622float2(*reinterpret_cast<const bf162*>(&X1[(size_t)m*NN + n]));
            float2 x1b = __bfloat1622float2(*reinterpret_cast<const bf162*>(&X1[(size_t)(m+8)*NN + n]));
            float v0 = acc[ms][ns][0] + bias0 + x1a.x;
            float v1 = acc[ms][ns][1] + bias0 + x1a.y;
            float v2 = acc[ms][ns][2] + bias1 + x1b.x;
            float v3 = acc[ms][ns][3] + bias1 + x1b.y;
            if (l < LL - 1) {
                v0 = gelu_exact(v0); v1 = gelu_exact(v1);
                v2 = gelu_exact(v2); v3 = gelu_exact(v3);
            }
            Hn[(size_t)m*NN + n]         = v0;
            Hn[(size_t)m*NN + n + 1]     = v1;
            Hn[(size_t)(m+8)*NN + n]     = v2;
            Hn[(size_t)(m+8)*NN + n + 1] = v3;
        }
    }
}

// -------- K6: head --------
__global__ void k_head(const float* __restrict__ w1, const float* __restrict__ b1,
                       const float* __restrict__ w2, const float* __restrict__ b2,
                       float* __restrict__ out, int cur) {
    __shared__ float sh[CC][32];
    __shared__ float red[CC][33];
    int b  = blockIdx.y;
    int n0 = blockIdx.x * 32;
    int f = threadIdx.x;
    const float* H = g_h[cur] + (size_t)b*CC*NN + n0;
    #pragma unroll 4
    for (int c4 = 0; c4 < CC; c4 += 4) {
        int row = c4 + (f >> 5);
        int col = f & 31;
        sh[row][col] = H[(size_t)row*NN + col];
    }
    __syncthreads();
    float acc[32];
    float bv = b1[f];
    #pragma unroll
    for (int j = 0; j < 32; j++) acc[j] = bv;
    for (int c = 0; c < CC; c++) {
        float w = __ldg(&w1[(size_t)c*FCD + f]);
        #pragma unroll
        for (int j = 0; j < 32; j++) acc[j] += sh[c][j] * w;
    }
    float w2f = __ldg(&w2[f]);
    #pragma unroll
    for (int j = 0; j < 32; j++)
        red[f][j] = gelu_exact(acc[j]) * w2f;
    __syncthreads();
    if (f < 32) {
        float s = b2[0];
        #pragma unroll 8
        for (int q = 0; q < CC; q++) s += red[q][f];
        out[(size_t)b*NN + n0 + f] = s;
    }
}

// -------- launch --------
extern "C" void kernel_launch(void* const* d_in, const int* in_sizes, int n_in,
                              void* d_out, int out_size) {
    (void)in_sizes; (void)n_in; (void)out_size;
    const float* x     = (const float*)d_in[0];
    const float* xf    = (const float*)d_in[1];
    const int*   ind   = (const int*)  d_in[2];
    const float* modes = (const float*)d_in[3];
    const float* fc0_w = (const float*)d_in[4];
    const float* fc0_b = (const float*)d_in[5];
    const float* wc    = (const float*)d_in[6];
    const float* ws    = (const float*)d_in[7];
    const float* w0    = (const float*)d_in[8];
    const float* convw = (const float*)d_in[9];
    const float* convb = (const float*)d_in[10];
    const float* fc1_w = (const float*)d_in[11];
    const float* fc1_b = (const float*)d_in[12];
    const float* fc2_w = (const float*)d_in[13];
    const float* fc2_b = (const float*)d_in[14];
    float* out = (float*)d_out;

    dim3 g1(NN/32, BB);
    k_basis<<<g1, 256>>>(xf, ind, modes);
    dim3 g2(NN/256, CC, BB);
    k_fc0<<<g2, 256>>>(x, fc0_w, fc0_b);
    dim3 g3(KK/64, CC/32, BB*FWD_S);
    k_fwd_tc<<<g3, 256>>>();
    k_comb<<<CC*KK/256, 256>>>();

    dim3 g4(CC/8, LL, KK/128);
    k_mix_all<<<g4, 256>>>(wc, ws);

    k_x0h<<<BB*CC, 256>>>();
    k_f0h_all<<<LL, BB*CC>>>(w0, convb);
    dim3 g5(NN/128, CC/64, BB*LL);
    k_inv_spec_all<<<g5, 256>>>();

    int cur = 0;
    for (int l = 0; l < LL; l++) {
        dim3 g6(NN/128, CC/64, BB);
        k_conv_tc<<<g6, 256>>>(convw, l, cur);
        cur ^= 1;
    }

    dim3 g7(NN/32, BB);
    k_head<<<g7, 128>>>(fc1_w, fc1_b, fc2_w, fc2_b, out, cur);
}